// round 7
// baseline (speedup 1.0000x reference)
#include <cuda_runtime.h>
#include <cuda_bf16.h>
#include <math.h>

#define NB 4096
#define IN_DIM 1024
#define HID 512
#define EMBED 128
#define NTOK 16
#define NCODES 1024
#define LATENT 2048
#define NTOKENS_TOTAL (NB * NTOK)          // 65536
#define QELEMS (NTOKENS_TOTAL * EMBED)     // 8388608
#define REC_ELEMS (NB * IN_DIM)            // 4194304

// weight pool offsets (elements) — transposed [N][K] layouts
#define OFF_EW1 0
#define OFF_EW2 524288
#define OFF_EW3 786432
#define OFF_DW1 1835008
#define OFF_DW2 2883584
#define OFF_DW3 3145728
#define OFF_CB  3670016
#define WPOOL_N 3801088

// ------------------------- scratch -------------------------
__device__ __nv_bfloat16 g_xh[NB * IN_DIM];
__device__ __nv_bfloat16 g_xl[NB * IN_DIM];
__device__ __nv_bfloat16 g_h1h[NB * HID];
__device__ __nv_bfloat16 g_h1l[NB * HID];
__device__ __nv_bfloat16 g_h2h[NB * HID];
__device__ __nv_bfloat16 g_h2l[NB * HID];
__device__ __nv_bfloat16 g_zh[NB * LATENT];
__device__ __nv_bfloat16 g_zl[NB * LATENT];
__device__ __nv_bfloat16 g_qh[NB * LATENT];
__device__ __nv_bfloat16 g_ql[NB * LATENT];
__device__ __nv_bfloat16 g_h3h[NB * HID];
__device__ __nv_bfloat16 g_h3l[NB * HID];
__device__ __nv_bfloat16 g_h4h[NB * HID];
__device__ __nv_bfloat16 g_h4l[NB * HID];
__device__ __nv_bfloat16 g_wh[WPOOL_N];
__device__ __nv_bfloat16 g_wl[WPOOL_N];
__device__ float  g_cnorm[NCODES];
__device__ int    g_idx[NTOKENS_TOTAL];
__device__ double g_loss;

__device__ __forceinline__ float gelu_exact(float x) {
    return 0.5f * x * (1.0f + erff(x * 0.70710678118654752440f));
}

__device__ __forceinline__ void mma16(float* d,
                                      unsigned a0, unsigned a1, unsigned a2, unsigned a3,
                                      unsigned b0, unsigned b1) {
    asm volatile(
        "mma.sync.aligned.m16n8k16.row.col.f32.bf16.bf16.f32 "
        "{%0,%1,%2,%3},{%4,%5,%6,%7},{%8,%9},{%0,%1,%2,%3};"
        : "+f"(d[0]), "+f"(d[1]), "+f"(d[2]), "+f"(d[3])
        : "r"(a0), "r"(a1), "r"(a2), "r"(a3), "r"(b0), "r"(b1));
}

__device__ __forceinline__ void ldm4(unsigned &r0, unsigned &r1, unsigned &r2, unsigned &r3,
                                     unsigned addr) {
    asm volatile("ldmatrix.sync.aligned.m8n8.x4.shared.b16 {%0,%1,%2,%3}, [%4];"
                 : "=r"(r0), "=r"(r1), "=r"(r2), "=r"(r3) : "r"(addr));
}

__device__ __forceinline__ void cpa16(__nv_bfloat16* dst, const __nv_bfloat16* src) {
    unsigned a = (unsigned)__cvta_generic_to_shared(dst);
    asm volatile("cp.async.cg.shared.global [%0], [%1], 16;" :: "r"(a), "l"(src));
}
#define CPA_COMMIT() asm volatile("cp.async.commit_group;")
#define CPA_WAIT0()  asm volatile("cp.async.wait_group 0;")

// ------------------------- prep kernels -------------------------
__global__ void pack_plane(const float* __restrict__ src,
                           __nv_bfloat16* __restrict__ hi, __nv_bfloat16* __restrict__ lo,
                           int n4)
{
    int i = blockIdx.x * blockDim.x + threadIdx.x;
    if (i < n4) {
        float4 v = ((const float4*)src)[i];
        __nv_bfloat16 h0 = __float2bfloat16(v.x);
        __nv_bfloat16 h1 = __float2bfloat16(v.y);
        __nv_bfloat16 h2 = __float2bfloat16(v.z);
        __nv_bfloat16 h3 = __float2bfloat16(v.w);
        __nv_bfloat162 hh0; hh0.x = h0; hh0.y = h1;
        __nv_bfloat162 hh1; hh1.x = h2; hh1.y = h3;
        __nv_bfloat162 ll0;
        ll0.x = __float2bfloat16(v.x - __bfloat162float(h0));
        ll0.y = __float2bfloat16(v.y - __bfloat162float(h1));
        __nv_bfloat162 ll1;
        ll1.x = __float2bfloat16(v.z - __bfloat162float(h2));
        ll1.y = __float2bfloat16(v.w - __bfloat162float(h3));
        ((__nv_bfloat162*)hi)[i * 2]     = hh0;
        ((__nv_bfloat162*)hi)[i * 2 + 1] = hh1;
        ((__nv_bfloat162*)lo)[i * 2]     = ll0;
        ((__nv_bfloat162*)lo)[i * 2 + 1] = ll1;
    }
}

__global__ void pack_wT(const float* __restrict__ W,
                        __nv_bfloat16* __restrict__ hi, __nv_bfloat16* __restrict__ lo,
                        int K, int N)
{
    __shared__ float t[32][33];
    const int n0 = blockIdx.x * 32, k0 = blockIdx.y * 32;
    const int tx = threadIdx.x, ty = threadIdx.y;
    #pragma unroll
    for (int r = 0; r < 32; r += 8)
        t[ty + r][tx] = W[(size_t)(k0 + ty + r) * N + n0 + tx];
    __syncthreads();
    #pragma unroll
    for (int r = 0; r < 32; r += 8) {
        float v = t[tx][ty + r];
        size_t o = (size_t)(n0 + ty + r) * K + k0 + tx;
        __nv_bfloat16 h = __float2bfloat16(v);
        hi[o] = h;
        lo[o] = __float2bfloat16(v - __bfloat162float(h));
    }
}

__global__ void code_norm_kernel(const float* __restrict__ cb) {
    int c = blockIdx.x * blockDim.x + threadIdx.x;
    if (c < NCODES) {
        float s = 0.f;
        #pragma unroll 4
        for (int d = 0; d < EMBED; d++) {
            float v = cb[c * EMBED + d];
            s = fmaf(v, v, s);
        }
        g_cnorm[c] = s;
    }
}

__global__ void zero_loss_kernel() { g_loss = 0.0; }

// =========================================================================
// bf16 3-term GEMM, 512 threads (16 warps, 4x4), warp tile 32x32.
// =========================================================================
#define GAS 5120   // 128*40 bf16 per plane buffer
#define GEMM_SMEM (8 * GAS * 2)   // 81920 bytes

template <int ACT, int SPLIT>
__global__ __launch_bounds__(512, 1)
void gemm_bf(const __nv_bfloat16* __restrict__ Ah, const __nv_bfloat16* __restrict__ Al,
             const __nv_bfloat16* __restrict__ Wh, const __nv_bfloat16* __restrict__ Wl,
             const float* __restrict__ bias,
             float* __restrict__ C,
             __nv_bfloat16* __restrict__ Ch, __nv_bfloat16* __restrict__ Cl,
             int M, int K, int N)
{
    extern __shared__ __align__(16) char smraw[];
    __nv_bfloat16* sm  = (__nv_bfloat16*)smraw;
    __nv_bfloat16* AsH = sm;               // [2][GAS]
    __nv_bfloat16* AsL = sm + 2 * GAS;
    __nv_bfloat16* WsH = sm + 4 * GAS;
    __nv_bfloat16* WsL = sm + 6 * GAS;
    const unsigned smu = (unsigned)__cvta_generic_to_shared(sm);

    const int tid  = threadIdx.x;
    const int m0   = blockIdx.y * 128;
    const int n0   = blockIdx.x * 128;
    const int warp = tid >> 5, lane = tid & 31;
    const int mw = (warp & 3) * 32;
    const int nw = (warp >> 2) * 32;
    const int g  = lane >> 2;
    const int tq = lane & 3;

    const int lmr = lane & 15, lmk = (lane >> 4) * 8;
    const int brow = ((lane >> 4) << 3) + (lane & 7);
    const int bk8  = ((lane >> 3) & 1) << 3;

    // staging: each thread loads 1 float4 per plane
    const int srow = tid >> 2;              // 0..127
    const int sfq  = (tid & 3) * 8;
    const size_t aoff = (size_t)(m0 + srow) * K + sfq;
    const size_t woff = (size_t)(n0 + srow) * K + sfq;
    const int s_off = srow * 40 + sfq;

    float acc[2][4][4] = {};

    float4 ah0 = *(const float4*)(Ah + aoff);
    float4 al0 = *(const float4*)(Al + aoff);
    float4 wh0 = *(const float4*)(Wh + woff);
    float4 wl0 = *(const float4*)(Wl + woff);
    *(float4*)&AsH[s_off] = ah0;
    *(float4*)&AsL[s_off] = al0;
    *(float4*)&WsH[s_off] = wh0;
    *(float4*)&WsL[s_off] = wl0;
    __syncthreads();

    const int KT = K >> 5;
    for (int kt = 0; kt < KT; kt++) {
        const int cur = kt & 1, nxt = cur ^ 1;
        if (kt + 1 < KT) {
            const size_t ao = aoff + (kt + 1) * 32;
            const size_t wo = woff + (kt + 1) * 32;
            ah0 = *(const float4*)(Ah + ao);
            al0 = *(const float4*)(Al + ao);
            wh0 = *(const float4*)(Wh + wo);
            wl0 = *(const float4*)(Wl + wo);
        }
        const unsigned aHb = smu + (unsigned)(cur * GAS) * 2;
        const unsigned aLb = smu + (unsigned)((2 + cur) * GAS) * 2;
        const unsigned wHb = smu + (unsigned)((4 + cur) * GAS) * 2;
        const unsigned wLb = smu + (unsigned)((6 + cur) * GAS) * 2;
        #pragma unroll
        for (int ks = 0; ks < 32; ks += 16) {
            unsigned ahr[2][4], alr[2][4];
            #pragma unroll
            for (int i = 0; i < 2; i++) {
                const unsigned eo = (unsigned)((mw + i * 16 + lmr) * 40 + ks + lmk) * 2;
                ldm4(ahr[i][0], ahr[i][1], ahr[i][2], ahr[i][3], aHb + eo);
                ldm4(alr[i][0], alr[i][1], alr[i][2], alr[i][3], aLb + eo);
            }
            unsigned bhr[4][2], blr[4][2];
            #pragma unroll
            for (int jp = 0; jp < 2; jp++) {
                const unsigned eo = (unsigned)((nw + jp * 16 + brow) * 40 + ks + bk8) * 2;
                ldm4(bhr[jp*2][0], bhr[jp*2][1], bhr[jp*2+1][0], bhr[jp*2+1][1], wHb + eo);
                ldm4(blr[jp*2][0], blr[jp*2][1], blr[jp*2+1][0], blr[jp*2+1][1], wLb + eo);
            }
            #pragma unroll
            for (int i = 0; i < 2; i++)
                #pragma unroll
                for (int j = 0; j < 4; j++) {
                    mma16(acc[i][j], ahr[i][0], ahr[i][1], ahr[i][2], ahr[i][3], bhr[j][0], bhr[j][1]);
                    mma16(acc[i][j], ahr[i][0], ahr[i][1], ahr[i][2], ahr[i][3], blr[j][0], blr[j][1]);
                    mma16(acc[i][j], alr[i][0], alr[i][1], alr[i][2], alr[i][3], bhr[j][0], bhr[j][1]);
                }
        }
        if (kt + 1 < KT) {
            *(float4*)&AsH[nxt * GAS + s_off] = ah0;
            *(float4*)&AsL[nxt * GAS + s_off] = al0;
            *(float4*)&WsH[nxt * GAS + s_off] = wh0;
            *(float4*)&WsL[nxt * GAS + s_off] = wl0;
            __syncthreads();
        }
    }

    // epilogue
    #pragma unroll
    for (int j = 0; j < 4; j++) {
        const int col = n0 + nw + j * 8 + tq * 2;
        const float b0 = bias[col], b1 = bias[col + 1];
        #pragma unroll
        for (int i = 0; i < 2; i++) {
            const int r = m0 + mw + i * 16 + g;
            float v0 = acc[i][j][0] + b0;
            float v1 = acc[i][j][1] + b1;
            float v2 = acc[i][j][2] + b0;
            float v3 = acc[i][j][3] + b1;
            if (ACT) { v0 = gelu_exact(v0); v1 = gelu_exact(v1); v2 = gelu_exact(v2); v3 = gelu_exact(v3); }
            const size_t o0 = (size_t)r * N + col;
            const size_t o1 = (size_t)(r + 8) * N + col;
            if (SPLIT) {
                __nv_bfloat16 h0 = __float2bfloat16(v0), h1 = __float2bfloat16(v1);
                __nv_bfloat16 h2 = __float2bfloat16(v2), h3 = __float2bfloat16(v3);
                __nv_bfloat162 hh0; hh0.x = h0; hh0.y = h1;
                __nv_bfloat162 hh1; hh1.x = h2; hh1.y = h3;
                __nv_bfloat162 ll0;
                ll0.x = __float2bfloat16(v0 - __bfloat162float(h0));
                ll0.y = __float2bfloat16(v1 - __bfloat162float(h1));
                __nv_bfloat162 ll1;
                ll1.x = __float2bfloat16(v2 - __bfloat162float(h2));
                ll1.y = __float2bfloat16(v3 - __bfloat162float(h3));
                *(__nv_bfloat162*)&Ch[o0] = hh0;
                *(__nv_bfloat162*)&Ch[o1] = hh1;
                *(__nv_bfloat162*)&Cl[o0] = ll0;
                *(__nv_bfloat162*)&Cl[o1] = ll1;
            } else {
                *(float2*)&C[o0] = make_float2(v0, v1);
                *(float2*)&C[o1] = make_float2(v2, v3);
            }
        }
    }
}

// =========================================================================
// VQ, 512 threads (16 warps, 2x8), warp tile 64x16.
// =========================================================================
#define ZPS 17408            // 128*136
#define VQ_SMEM (((size_t)6 * ZPS) * 2 + NCODES * 4)

__global__ __launch_bounds__(512, 1)
void vq_kernel(const __nv_bfloat16* __restrict__ zh, const __nv_bfloat16* __restrict__ zl,
               const __nv_bfloat16* __restrict__ cbh, const __nv_bfloat16* __restrict__ cbl,
               const float* __restrict__ cb,
               __nv_bfloat16* __restrict__ qh, __nv_bfloat16* __restrict__ ql)
{
    extern __shared__ __align__(16) char smraw[];
    __nv_bfloat16* sm  = (__nv_bfloat16*)smraw;
    __nv_bfloat16* ZsH = sm;
    __nv_bfloat16* ZsL = sm + ZPS;
    __nv_bfloat16* Cb  = sm + 2 * ZPS;
    float* cn = (float*)(sm + 6 * ZPS);
    const unsigned smu = (unsigned)__cvta_generic_to_shared(sm);

    __shared__ float red_d[128][8];
    __shared__ int   red_i[128][8];
    __shared__ int   best_idx[128];
    __shared__ float warp_sum[16];

    const int tid = threadIdx.x;
    const int t0  = blockIdx.x * 128;
    const int warp = tid >> 5, lane = tid & 31;
    const int mw = (warp & 1) * 64;
    const int nw = (warp >> 1) * 16;
    const int g  = lane >> 2;
    const int tq = lane & 3;

    const int lmr = lane & 15, lmk = (lane >> 4) * 8;
    const int brow = ((lane >> 4) << 3) + (lane & 7);
    const int bk8  = ((lane >> 3) & 1) << 3;

    if (tid < 256) *(float4*)&cn[tid * 4] = *(const float4*)&g_cnorm[tid * 4];

    #pragma unroll
    for (int l = 0; l < 4; l++) {
        int idx = l * 512 + tid;
        int row = idx >> 4, c16 = (idx & 15) * 8;
        cpa16(ZsH + row * 136 + c16, zh + (size_t)(t0 + row) * EMBED + c16);
        cpa16(ZsL + row * 136 + c16, zl + (size_t)(t0 + row) * EMBED + c16);
        cpa16(Cb + row * 136 + c16,        cbh + (size_t)row * EMBED + c16);
        cpa16(Cb + ZPS + row * 136 + c16,  cbl + (size_t)row * EMBED + c16);
    }
    CPA_COMMIT();
    CPA_WAIT0();
    __syncthreads();

    float bestD[8];
    int   bestI[8];
    #pragma unroll
    for (int s = 0; s < 8; s++) { bestD[s] = 3.4e38f; bestI[s] = 0; }

    for (int ct = 0; ct < 8; ct++) {
        const int cur = ct & 1, nxt = cur ^ 1;
        const unsigned cHb = smu + (unsigned)(2 * ZPS + cur * 2 * ZPS) * 2;
        const unsigned cLb = cHb + (unsigned)ZPS * 2;

        if (ct < 7) {
            const int c0n = (ct + 1) * 128;
            __nv_bfloat16* dH = Cb + nxt * 2 * ZPS;
            __nv_bfloat16* dL = dH + ZPS;
            #pragma unroll
            for (int l = 0; l < 4; l++) {
                int idx = l * 512 + tid;
                int row = idx >> 4, c16 = (idx & 15) * 8;
                cpa16(dH + row * 136 + c16, cbh + (size_t)(c0n + row) * EMBED + c16);
                cpa16(dL + row * 136 + c16, cbl + (size_t)(c0n + row) * EMBED + c16);
            }
            CPA_COMMIT();
        }

        float acc[4][2][4] = {};
        #pragma unroll
        for (int kt = 0; kt < 8; kt++) {
            const int kb = kt * 16;
            unsigned ahr[4][4], alr[4][4];
            #pragma unroll
            for (int i = 0; i < 4; i++) {
                const unsigned eo = (unsigned)((mw + i * 16 + lmr) * 136 + kb + lmk) * 2;
                ldm4(ahr[i][0], ahr[i][1], ahr[i][2], ahr[i][3], smu + eo);
                ldm4(alr[i][0], alr[i][1], alr[i][2], alr[i][3], smu + (unsigned)ZPS * 2 + eo);
            }
            unsigned bhr[2][2], blr[2][2];
            {
                const unsigned eo = (unsigned)((nw + brow) * 136 + kb + bk8) * 2;
                ldm4(bhr[0][0], bhr[0][1], bhr[1][0], bhr[1][1], cHb + eo);
                ldm4(blr[0][0], blr[0][1], blr[1][0], blr[1][1], cLb + eo);
            }
            #pragma unroll
            for (int i = 0; i < 4; i++)
                #pragma unroll
                for (int j = 0; j < 2; j++) {
                    mma16(acc[i][j], ahr[i][0], ahr[i][1], ahr[i][2], ahr[i][3], bhr[j][0], bhr[j][1]);
                    mma16(acc[i][j], ahr[i][0], ahr[i][1], ahr[i][2], ahr[i][3], blr[j][0], blr[j][1]);
                    mma16(acc[i][j], alr[i][0], alr[i][1], alr[i][2], alr[i][3], bhr[j][0], bhr[j][1]);
                }
        }

        const int c0 = ct * 128;
        #pragma unroll
        for (int j = 0; j < 2; j++) {
            const int cbase = c0 + nw + j * 8 + tq * 2;
            const float cn0 = cn[cbase], cn1 = cn[cbase + 1];
            #pragma unroll
            for (int i = 0; i < 4; i++) {
                #pragma unroll
                for (int h = 0; h < 2; h++) {
                    const int s = i * 2 + h;
                    float d0 = fmaf(-2.0f, acc[i][j][h * 2 + 0], cn0);
                    float d1 = fmaf(-2.0f, acc[i][j][h * 2 + 1], cn1);
                    if (d0 < bestD[s] || (d0 == bestD[s] && cbase < bestI[s])) { bestD[s] = d0; bestI[s] = cbase; }
                    if (d1 < bestD[s] || (d1 == bestD[s] && cbase + 1 < bestI[s])) { bestD[s] = d1; bestI[s] = cbase + 1; }
                }
            }
        }

        if (ct < 7) {
            CPA_WAIT0();
            __syncthreads();
        }
    }

    // reduce across tq lanes
    #pragma unroll
    for (int s = 0; s < 8; s++) {
        #pragma unroll
        for (int o = 1; o < 4; o <<= 1) {
            float od = __shfl_xor_sync(0xFFFFFFFFu, bestD[s], o);
            int   oi = __shfl_xor_sync(0xFFFFFFFFu, bestI[s], o);
            if (od < bestD[s] || (od == bestD[s] && oi < bestI[s])) { bestD[s] = od; bestI[s] = oi; }
        }
    }
    if (tq == 0) {
        #pragma unroll
        for (int s = 0; s < 8; s++) {
            const int row = mw + (s >> 1) * 16 + (s & 1) * 8 + g;
            red_d[row][warp >> 1] = bestD[s];
            red_i[row][warp >> 1] = bestI[s];
        }
    }
    __syncthreads();
    if (tid < 128) {
        float bd = red_d[tid][0];
        int   bi = red_i[tid][0];
        #pragma unroll
        for (int x = 1; x < 8; x++) {
            float d = red_d[tid][x];
            int   c = red_i[tid][x];
            if (d < bd || (d == bd && c < bi)) { bd = d; bi = c; }
        }
        best_idx[tid] = bi;
        g_idx[t0 + tid] = bi;
    }
    __syncthreads();

    // gather + straight-through + commit loss
    float lsum = 0.f;
    #pragma unroll 4
    for (int l = 0; l < 32; l++) {
        int e = l * 512 + tid;
        int trow = e >> 7;
        int d    = e & 127;
        int c    = best_idx[trow];
        float zv = __bfloat162float(ZsH[trow * 136 + d]) + __bfloat162float(ZsL[trow * 136 + d]);
        float diff = cb[(size_t)c * EMBED + d] - zv;
        float qv = zv + diff;
        __nv_bfloat16 hh = __float2bfloat16(qv);
        size_t go = (size_t)t0 * EMBED + e;
        qh[go] = hh;
        ql[go] = __float2bfloat16(qv - __bfloat162float(hh));
        lsum = fmaf(diff, diff, lsum);
    }
    #pragma unroll
    for (int o = 16; o > 0; o >>= 1) lsum += __shfl_down_sync(0xFFFFFFFFu, lsum, o);
    if (lane == 0) warp_sum[warp] = lsum;
    __syncthreads();
    if (tid == 0) {
        float s = 0.f;
        #pragma unroll
        for (int w = 0; w < 16; w++) s += warp_sum[w];
        atomicAdd(&g_loss, (double)s);
    }
}

// ------------------------- tail outputs -------------------------
__global__ void finalize_kernel(float* __restrict__ out)
{
    int i = blockIdx.x * 256 + threadIdx.x;
    if (i < NTOKENS_TOTAL) out[REC_ELEMS + i] = (float)g_idx[i];
    if (i == 0) out[REC_ELEMS + NTOKENS_TOTAL] = (float)(g_loss / (double)QELEMS);
}

// ------------------------- launch -------------------------
extern "C" void kernel_launch(void* const* d_in, const int* in_sizes, int n_in,
                              void* d_out, int out_size)
{
    const float* x   = (const float*)d_in[0];
    const float* eW1 = (const float*)d_in[1];
    const float* eb1 = (const float*)d_in[2];
    const float* eW2 = (const float*)d_in[3];
    const float* eb2 = (const float*)d_in[4];
    const float* eW3 = (const float*)d_in[5];
    const float* eb3 = (const float*)d_in[6];
    const float* dW1 = (const float*)d_in[7];
    const float* db1 = (const float*)d_in[8];
    const float* dW2 = (const float*)d_in[9];
    const float* db2 = (const float*)d_in[10];
    const float* dW3 = (const float*)d_in[11];
    const float* db3 = (const float*)d_in[12];
    const float* cb  = (const float*)d_in[13];
    float* out = (float*)d_out;

    __nv_bfloat16 *xh, *xl, *h1h, *h1l, *h2h, *h2l, *zh, *zl, *qh, *ql;
    __nv_bfloat16 *h3h, *h3l, *h4h, *h4l, *wh, *wl;
    cudaGetSymbolAddress((void**)&xh,  g_xh);
    cudaGetSymbolAddress((void**)&xl,  g_xl);
    cudaGetSymbolAddress((void**)&h1h, g_h1h);
    cudaGetSymbolAddress((void**)&h1l, g_h1l);
    cudaGetSymbolAddress((void**)&h2h, g_h2h);
    cudaGetSymbolAddress((void**)&h2l, g_h2l);
    cudaGetSymbolAddress((void**)&zh,  g_zh);
    cudaGetSymbolAddress((void**)&zl,  g_zl);
    cudaGetSymbolAddress((void**)&qh,  g_qh);
    cudaGetSymbolAddress((void**)&ql,  g_ql);
    cudaGetSymbolAddress((void**)&h3h, g_h3h);
    cudaGetSymbolAddress((void**)&h3l, g_h3l);
    cudaGetSymbolAddress((void**)&h4h, g_h4h);
    cudaGetSymbolAddress((void**)&h4l, g_h4l);
    cudaGetSymbolAddress((void**)&wh,  g_wh);
    cudaGetSymbolAddress((void**)&wl,  g_wl);

    cudaFuncSetAttribute(gemm_bf<1, 1>, cudaFuncAttributeMaxDynamicSharedMemorySize, GEMM_SMEM);
    cudaFuncSetAttribute(gemm_bf<0, 1>, cudaFuncAttributeMaxDynamicSharedMemorySize, GEMM_SMEM);
    cudaFuncSetAttribute(gemm_bf<0, 0>, cudaFuncAttributeMaxDynamicSharedMemorySize, GEMM_SMEM);
    cudaFuncSetAttribute(vq_kernel, cudaFuncAttributeMaxDynamicSharedMemorySize, (int)VQ_SMEM);

    zero_loss_kernel<<<1, 1>>>();
    code_norm_kernel<<<4, 256>>>(cb);

    pack_plane<<<(NB * IN_DIM / 4 + 255) / 256, 256>>>(x,  xh, xl, NB * IN_DIM / 4);
    pack_plane<<<(NCODES * EMBED / 4 + 255) / 256, 256>>>(cb, wh + OFF_CB, wl + OFF_CB, NCODES * EMBED / 4);
    dim3 tb(32, 8);
    pack_wT<<<dim3(HID / 32,    IN_DIM / 32), tb>>>(eW1, wh + OFF_EW1, wl + OFF_EW1, IN_DIM, HID);
    pack_wT<<<dim3(HID / 32,    HID / 32),    tb>>>(eW2, wh + OFF_EW2, wl + OFF_EW2, HID,    HID);
    pack_wT<<<dim3(LATENT / 32, HID / 32),    tb>>>(eW3, wh + OFF_EW3, wl + OFF_EW3, HID,    LATENT);
    pack_wT<<<dim3(HID / 32,    LATENT / 32), tb>>>(dW1, wh + OFF_DW1, wl + OFF_DW1, LATENT, HID);
    pack_wT<<<dim3(HID / 32,    HID / 32),    tb>>>(dW2, wh + OFF_DW2, wl + OFF_DW2, HID,    HID);
    pack_wT<<<dim3(IN_DIM / 32, HID / 32),    tb>>>(dW3, wh + OFF_DW3, wl + OFF_DW3, HID,    IN_DIM);

    gemm_bf<1, 1><<<dim3(HID / 128,    NB / 128), 512, GEMM_SMEM>>>(
        xh, xl, wh + OFF_EW1, wl + OFF_EW1, eb1, nullptr, h1h, h1l, NB, IN_DIM, HID);
    gemm_bf<1, 1><<<dim3(HID / 128,    NB / 128), 512, GEMM_SMEM>>>(
        h1h, h1l, wh + OFF_EW2, wl + OFF_EW2, eb2, nullptr, h2h, h2l, NB, HID, HID);
    gemm_bf<0, 1><<<dim3(LATENT / 128, NB / 128), 512, GEMM_SMEM>>>(
        h2h, h2l, wh + OFF_EW3, wl + OFF_EW3, eb3, nullptr, zh, zl, NB, HID, LATENT);

    vq_kernel<<<NTOKENS_TOTAL / 128, 512, VQ_SMEM>>>(
        zh, zl, wh + OFF_CB, wl + OFF_CB, cb, qh, ql);

    gemm_bf<1, 1><<<dim3(HID / 128,    NB / 128), 512, GEMM_SMEM>>>(
        qh, ql, wh + OFF_DW1, wl + OFF_DW1, db1, nullptr, h3h, h3l, NB, LATENT, HID);
    gemm_bf<1, 1><<<dim3(HID / 128,    NB / 128), 512, GEMM_SMEM>>>(
        h3h, h3l, wh + OFF_DW2, wl + OFF_DW2, db2, nullptr, h4h, h4l, NB, HID, HID);
    gemm_bf<0, 0><<<dim3(IN_DIM / 128, NB / 128), 512, GEMM_SMEM>>>(
        h4h, h4l, wh + OFF_DW3, wl + OFF_DW3, db3, out, nullptr, nullptr, NB, HID, IN_DIM);

    if (out_size >= REC_ELEMS + NTOKENS_TOTAL + 1)
        finalize_kernel<<<(NTOKENS_TOTAL + 255) / 256, 256>>>(out);
}

// round 9
// speedup vs baseline: 1.0895x; 1.0895x over previous
#include <cuda_runtime.h>
#include <cuda_bf16.h>
#include <math.h>

#define NB 4096
#define IN_DIM 1024
#define HID 512
#define EMBED 128
#define NTOK 16
#define NCODES 1024
#define LATENT 2048
#define NTOKENS_TOTAL (NB * NTOK)          // 65536
#define QELEMS (NTOKENS_TOTAL * EMBED)     // 8388608
#define REC_ELEMS (NB * IN_DIM)            // 4194304

// weight pool offsets (elements) — transposed [N][K] layouts
#define OFF_EW1 0
#define OFF_EW2 524288
#define OFF_EW3 786432
#define OFF_DW1 1835008
#define OFF_DW2 2883584
#define OFF_DW3 3145728
#define OFF_CB  3670016
#define WPOOL_N 3801088

// ------------------------- scratch -------------------------
__device__ __nv_bfloat16 g_xh[NB * IN_DIM];
__device__ __nv_bfloat16 g_xl[NB * IN_DIM];
__device__ __nv_bfloat16 g_h1h[NB * HID];
__device__ __nv_bfloat16 g_h1l[NB * HID];
__device__ __nv_bfloat16 g_h2h[NB * HID];
__device__ __nv_bfloat16 g_h2l[NB * HID];
__device__ __nv_bfloat16 g_zh[NB * LATENT];
__device__ __nv_bfloat16 g_zl[NB * LATENT];
__device__ __nv_bfloat16 g_h3h[NB * HID];
__device__ __nv_bfloat16 g_h3l[NB * HID];
__device__ __nv_bfloat16 g_h4h[NB * HID];
__device__ __nv_bfloat16 g_h4l[NB * HID];
__device__ __nv_bfloat16 g_wh[WPOOL_N];
__device__ __nv_bfloat16 g_wl[WPOOL_N];
__device__ float  g_T[NTOK * NCODES * HID];   // 33.5 MB code table
__device__ float  g_cnorm[NCODES];
__device__ int    g_idx[NTOKENS_TOTAL];
__device__ double g_loss;

__device__ __forceinline__ float gelu_exact(float x) {
    return 0.5f * x * (1.0f + erff(x * 0.70710678118654752440f));
}

__device__ __forceinline__ void mma16(float* d,
                                      unsigned a0, unsigned a1, unsigned a2, unsigned a3,
                                      unsigned b0, unsigned b1) {
    asm volatile(
        "mma.sync.aligned.m16n8k16.row.col.f32.bf16.bf16.f32 "
        "{%0,%1,%2,%3},{%4,%5,%6,%7},{%8,%9},{%0,%1,%2,%3};"
        : "+f"(d[0]), "+f"(d[1]), "+f"(d[2]), "+f"(d[3])
        : "r"(a0), "r"(a1), "r"(a2), "r"(a3), "r"(b0), "r"(b1));
}

__device__ __forceinline__ void ldm4(unsigned &r0, unsigned &r1, unsigned &r2, unsigned &r3,
                                     unsigned addr) {
    asm volatile("ldmatrix.sync.aligned.m8n8.x4.shared.b16 {%0,%1,%2,%3}, [%4];"
                 : "=r"(r0), "=r"(r1), "=r"(r2), "=r"(r3) : "r"(addr));
}

__device__ __forceinline__ void cpa16(__nv_bfloat16* dst, const __nv_bfloat16* src) {
    unsigned a = (unsigned)__cvta_generic_to_shared(dst);
    asm volatile("cp.async.cg.shared.global [%0], [%1], 16;" :: "r"(a), "l"(src));
}
__device__ __forceinline__ void cpa16u(unsigned dst, const __nv_bfloat16* src) {
    asm volatile("cp.async.cg.shared.global [%0], [%1], 16;" :: "r"(dst), "l"(src));
}
#define CPA_COMMIT() asm volatile("cp.async.commit_group;")
#define CPA_WAIT0()  asm volatile("cp.async.wait_group 0;")
#define CPA_WAIT1()  asm volatile("cp.async.wait_group 1;")

// ------------------------- prep kernels -------------------------
__device__ __forceinline__ void split_f4(float4 v, __nv_bfloat16* hi, __nv_bfloat16* lo, int i) {
    __nv_bfloat16 h0 = __float2bfloat16(v.x);
    __nv_bfloat16 h1 = __float2bfloat16(v.y);
    __nv_bfloat16 h2 = __float2bfloat16(v.z);
    __nv_bfloat16 h3 = __float2bfloat16(v.w);
    __nv_bfloat162 hh0; hh0.x = h0; hh0.y = h1;
    __nv_bfloat162 hh1; hh1.x = h2; hh1.y = h3;
    __nv_bfloat162 ll0;
    ll0.x = __float2bfloat16(v.x - __bfloat162float(h0));
    ll0.y = __float2bfloat16(v.y - __bfloat162float(h1));
    __nv_bfloat162 ll1;
    ll1.x = __float2bfloat16(v.z - __bfloat162float(h2));
    ll1.y = __float2bfloat16(v.w - __bfloat162float(h3));
    ((__nv_bfloat162*)hi)[i * 2]     = hh0;
    ((__nv_bfloat162*)hi)[i * 2 + 1] = hh1;
    ((__nv_bfloat162*)lo)[i * 2]     = ll0;
    ((__nv_bfloat162*)lo)[i * 2 + 1] = ll1;
}

#define X4  (NB * IN_DIM / 4)       // 1048576
#define CB4 (NCODES * EMBED / 4)    // 32768

// pack x and codebook planes in one kernel
__global__ void pack_all(const float* __restrict__ x, const float* __restrict__ cb,
                         __nv_bfloat16* __restrict__ xh, __nv_bfloat16* __restrict__ xl,
                         __nv_bfloat16* __restrict__ ch, __nv_bfloat16* __restrict__ cl)
{
    int i = blockIdx.x * blockDim.x + threadIdx.x;
    if (i < X4) {
        split_f4(((const float4*)x)[i], xh, xl, i);
    } else if (i < X4 + CB4) {
        int j = i - X4;
        split_f4(((const float4*)cb)[j], ch, cl, j);
    }
}

// all 6 weight transposes in one launch; tile table hardcoded
__global__ void packT_all(const float* __restrict__ eW1, const float* __restrict__ eW2,
                          const float* __restrict__ eW3, const float* __restrict__ dW1,
                          const float* __restrict__ dW2, const float* __restrict__ dW3,
                          __nv_bfloat16* __restrict__ wh, __nv_bfloat16* __restrict__ wl)
{
    __shared__ float t[32][33];
    int bid = blockIdx.x;
    const float* W; int K, N, off, lt;
    if      (bid < 512)  { W = eW1; K = IN_DIM; N = HID;    off = OFF_EW1; lt = bid; }
    else if (bid < 768)  { W = eW2; K = HID;    N = HID;    off = OFF_EW2; lt = bid - 512; }
    else if (bid < 1792) { W = eW3; K = HID;    N = LATENT; off = OFF_EW3; lt = bid - 768; }
    else if (bid < 2816) { W = dW1; K = LATENT; N = HID;    off = OFF_DW1; lt = bid - 1792; }
    else if (bid < 3072) { W = dW2; K = HID;    N = HID;    off = OFF_DW2; lt = bid - 2816; }
    else                 { W = dW3; K = HID;    N = IN_DIM; off = OFF_DW3; lt = bid - 3072; }
    const int ntn = N >> 5;
    const int n0 = (lt % ntn) * 32, k0 = (lt / ntn) * 32;
    const int tx = threadIdx.x, ty = threadIdx.y;
    #pragma unroll
    for (int r = 0; r < 32; r += 8)
        t[ty + r][tx] = W[(size_t)(k0 + ty + r) * N + n0 + tx];
    __syncthreads();
    #pragma unroll
    for (int r = 0; r < 32; r += 8) {
        float v = t[tx][ty + r];
        size_t o = (size_t)off + (size_t)(n0 + ty + r) * K + k0 + tx;
        __nv_bfloat16 h = __float2bfloat16(v);
        g_wh[o] = h;
        g_wl[o] = __float2bfloat16(v - __bfloat162float(h));
    }
    (void)wh; (void)wl;
}

__global__ void code_norm_kernel(const float* __restrict__ cb) {
    int c = blockIdx.x * blockDim.x + threadIdx.x;
    if (c == 0) g_loss = 0.0;
    if (c < NCODES) {
        float s = 0.f;
        #pragma unroll 4
        for (int d = 0; d < EMBED; d++) {
            float v = cb[c * EMBED + d];
            s = fmaf(v, v, s);
        }
        g_cnorm[c] = s;
    }
}

// =========================================================================
// bf16 3-term GEMM, cp.async 3-stage, 256 thr (8 warps 2x4), ldmatrix.
// smem stage: 4 planes (AH,AL,WH,WL) x [128][40] bf16
// =========================================================================
#define GPLANE 5120                  // 128*40 elems
#define GSTAGE (4 * GPLANE)          // 20480 elems
#define GEMM_SMEM (3 * GSTAGE * 2)   // 122880 bytes

template <int ACT, int SPLIT>
__global__ __launch_bounds__(256, 1)
void gemm_bf(const __nv_bfloat16* __restrict__ Ah, const __nv_bfloat16* __restrict__ Al,
             const __nv_bfloat16* __restrict__ Wh, const __nv_bfloat16* __restrict__ Wl,
             const float* __restrict__ bias,
             float* __restrict__ C,
             __nv_bfloat16* __restrict__ Ch, __nv_bfloat16* __restrict__ Cl,
             int M, int K, int N)
{
    extern __shared__ __align__(16) char smraw[];
    const unsigned smu = (unsigned)__cvta_generic_to_shared(smraw);

    const int tid  = threadIdx.x;
    const int m0   = blockIdx.y * 128;
    const int n0   = blockIdx.x * 128;
    const int warp = tid >> 5, lane = tid & 31;
    const int mw = (warp & 1) * 64;
    const int nw = (warp >> 1) * 32;
    const int g  = lane >> 2;
    const int tq = lane & 3;

    const int lmr = lane & 15, lmk = (lane >> 4) * 8;
    const int brow = ((lane >> 4) << 3) + (lane & 7);
    const int bk8  = ((lane >> 3) & 1) << 3;

    const __nv_bfloat16* sp0 = Ah + (size_t)m0 * K;
    const __nv_bfloat16* sp1 = Al + (size_t)m0 * K;
    const __nv_bfloat16* sp2 = Wh + (size_t)n0 * K;
    const __nv_bfloat16* sp3 = Wl + (size_t)n0 * K;

    const int KT = K >> 5;

    // fill stage s with K-chunk kt: 2048 16B chunks, 8 per thread
    auto fill = [&](int kt, int s) {
        const __nv_bfloat16* sp[4] = { sp0 + kt * 32, sp1 + kt * 32, sp2 + kt * 32, sp3 + kt * 32 };
        #pragma unroll
        for (int l = 0; l < 8; l++) {
            int c = l * 256 + tid;
            int p = c >> 9;
            int r = (c >> 2) & 127;
            int q = c & 3;
            cpa16u(smu + (unsigned)(s * GSTAGE + p * GPLANE + r * 40 + q * 8) * 2,
                   sp[p] + (size_t)r * K + q * 8);
        }
        CPA_COMMIT();
    };

    fill(0, 0);
    fill(1, 1);

    float acc[4][4][4] = {};

    for (int kt = 0; kt < KT; kt++) {
        if (kt + 1 < KT) { CPA_WAIT1(); } else { CPA_WAIT0(); }
        __syncthreads();
        if (kt + 2 < KT) fill(kt + 2, (kt + 2) % 3);

        const int s = kt % 3;
        const unsigned aHb = smu + (unsigned)(s * GSTAGE) * 2;
        const unsigned aLb = aHb + (unsigned)GPLANE * 2;
        const unsigned wHb = aLb + (unsigned)GPLANE * 2;
        const unsigned wLb = wHb + (unsigned)GPLANE * 2;
        #pragma unroll
        for (int ks = 0; ks < 32; ks += 16) {
            unsigned ahr[4][4], alr[4][4];
            #pragma unroll
            for (int i = 0; i < 4; i++) {
                const unsigned eo = (unsigned)((mw + i * 16 + lmr) * 40 + ks + lmk) * 2;
                ldm4(ahr[i][0], ahr[i][1], ahr[i][2], ahr[i][3], aHb + eo);
                ldm4(alr[i][0], alr[i][1], alr[i][2], alr[i][3], aLb + eo);
            }
            unsigned bhr[4][2], blr[4][2];
            #pragma unroll
            for (int jp = 0; jp < 2; jp++) {
                const unsigned eo = (unsigned)((nw + jp * 16 + brow) * 40 + ks + bk8) * 2;
                ldm4(bhr[jp*2][0], bhr[jp*2][1], bhr[jp*2+1][0], bhr[jp*2+1][1], wHb + eo);
                ldm4(blr[jp*2][0], blr[jp*2][1], blr[jp*2+1][0], blr[jp*2+1][1], wLb + eo);
            }
            #pragma unroll
            for (int i = 0; i < 4; i++)
                #pragma unroll
                for (int j = 0; j < 4; j++) {
                    mma16(acc[i][j], ahr[i][0], ahr[i][1], ahr[i][2], ahr[i][3], bhr[j][0], bhr[j][1]);
                    mma16(acc[i][j], ahr[i][0], ahr[i][1], ahr[i][2], ahr[i][3], blr[j][0], blr[j][1]);
                    mma16(acc[i][j], alr[i][0], alr[i][1], alr[i][2], alr[i][3], bhr[j][0], bhr[j][1]);
                }
        }
        __syncthreads();   // stage s free for refill next iterations
    }

    // epilogue
    #pragma unroll
    for (int j = 0; j < 4; j++) {
        const int col = n0 + nw + j * 8 + tq * 2;
        const float b0 = bias[col], b1 = bias[col + 1];
        #pragma unroll
        for (int i = 0; i < 4; i++) {
            const int r = m0 + mw + i * 16 + g;
            float v0 = acc[i][j][0] + b0;
            float v1 = acc[i][j][1] + b1;
            float v2 = acc[i][j][2] + b0;
            float v3 = acc[i][j][3] + b1;
            if (ACT) { v0 = gelu_exact(v0); v1 = gelu_exact(v1); v2 = gelu_exact(v2); v3 = gelu_exact(v3); }
            const size_t o0 = (size_t)r * N + col;
            const size_t o1 = (size_t)(r + 8) * N + col;
            if (SPLIT) {
                __nv_bfloat16 h0 = __float2bfloat16(v0), h1 = __float2bfloat16(v1);
                __nv_bfloat16 h2 = __float2bfloat16(v2), h3 = __float2bfloat16(v3);
                __nv_bfloat162 hh0; hh0.x = h0; hh0.y = h1;
                __nv_bfloat162 hh1; hh1.x = h2; hh1.y = h3;
                __nv_bfloat162 ll0;
                ll0.x = __float2bfloat16(v0 - __bfloat162float(h0));
                ll0.y = __float2bfloat16(v1 - __bfloat162float(h1));
                __nv_bfloat162 ll1;
                ll1.x = __float2bfloat16(v2 - __bfloat162float(h2));
                ll1.y = __float2bfloat16(v3 - __bfloat162float(h3));
                *(__nv_bfloat162*)&Ch[o0] = hh0;
                *(__nv_bfloat162*)&Ch[o1] = hh1;
                *(__nv_bfloat162*)&Cl[o0] = ll0;
                *(__nv_bfloat162*)&Cl[o1] = ll1;
            } else {
                *(float2*)&C[o0] = make_float2(v0, v1);
                *(float2*)&C[o1] = make_float2(v2, v3);
            }
        }
    }
}

// =========================================================================
// Code table: T[t][c][n] = cb[c] @ dW1[t*128:(t+1)*128, n]  (no bias/act)
// A = cb planes [1024][128]; W = dW1 planes [512][2048], k-offset t*128.
// grid (4 n, 8 m, 16 t), 256 thr; K=128 (KT=4).
// =========================================================================
__global__ __launch_bounds__(256, 1)
void gemm_tab(const __nv_bfloat16* __restrict__ Ah, const __nv_bfloat16* __restrict__ Al,
              const __nv_bfloat16* __restrict__ Wh, const __nv_bfloat16* __restrict__ Wl)
{
    extern __shared__ __align__(16) char smraw[];
    const unsigned smu = (unsigned)__cvta_generic_to_shared(smraw);

    const int tid  = threadIdx.x;
    const int m0   = blockIdx.y * 128;
    const int n0   = blockIdx.x * 128;
    const int tt   = blockIdx.z;
    const int warp = tid >> 5, lane = tid & 31;
    const int mw = (warp & 1) * 64;
    const int nw = (warp >> 1) * 32;
    const int g  = lane >> 2;
    const int tq = lane & 3;

    const int lmr = lane & 15, lmk = (lane >> 4) * 8;
    const int brow = ((lane >> 4) << 3) + (lane & 7);
    const int bk8  = ((lane >> 3) & 1) << 3;

    const int AK = EMBED;          // 128
    const int WK = LATENT;         // 2048
    const int koff = tt * EMBED;

    const __nv_bfloat16* sp0 = Ah + (size_t)m0 * AK;
    const __nv_bfloat16* sp1 = Al + (size_t)m0 * AK;
    const __nv_bfloat16* sp2 = Wh + (size_t)n0 * WK + koff;
    const __nv_bfloat16* sp3 = Wl + (size_t)n0 * WK + koff;

    const int KT = 4;

    auto fill = [&](int kt, int s) {
        #pragma unroll
        for (int l = 0; l < 8; l++) {
            int c = l * 256 + tid;
            int p = c >> 9;
            int r = (c >> 2) & 127;
            int q = c & 3;
            const __nv_bfloat16* src;
            if (p == 0)      src = sp0 + (size_t)r * AK;
            else if (p == 1) src = sp1 + (size_t)r * AK;
            else if (p == 2) src = sp2 + (size_t)r * WK;
            else             src = sp3 + (size_t)r * WK;
            cpa16u(smu + (unsigned)(s * GSTAGE + p * GPLANE + r * 40 + q * 8) * 2,
                   src + kt * 32 + q * 8);
        }
        CPA_COMMIT();
    };

    fill(0, 0);
    fill(1, 1);

    float acc[4][4][4] = {};

    for (int kt = 0; kt < KT; kt++) {
        if (kt + 1 < KT) { CPA_WAIT1(); } else { CPA_WAIT0(); }
        __syncthreads();
        if (kt + 2 < KT) fill(kt + 2, (kt + 2) % 3);

        const int s = kt % 3;
        const unsigned aHb = smu + (unsigned)(s * GSTAGE) * 2;
        const unsigned aLb = aHb + (unsigned)GPLANE * 2;
        const unsigned wHb = aLb + (unsigned)GPLANE * 2;
        const unsigned wLb = wHb + (unsigned)GPLANE * 2;
        #pragma unroll
        for (int ks = 0; ks < 32; ks += 16) {
            unsigned ahr[4][4], alr[4][4];
            #pragma unroll
            for (int i = 0; i < 4; i++) {
                const unsigned eo = (unsigned)((mw + i * 16 + lmr) * 40 + ks + lmk) * 2;
                ldm4(ahr[i][0], ahr[i][1], ahr[i][2], ahr[i][3], aHb + eo);
                ldm4(alr[i][0], alr[i][1], alr[i][2], alr[i][3], aLb + eo);
            }
            unsigned bhr[4][2], blr[4][2];
            #pragma unroll
            for (int jp = 0; jp < 2; jp++) {
                const unsigned eo = (unsigned)((nw + jp * 16 + brow) * 40 + ks + bk8) * 2;
                ldm4(bhr[jp*2][0], bhr[jp*2][1], bhr[jp*2+1][0], bhr[jp*2+1][1], wHb + eo);
                ldm4(blr[jp*2][0], blr[jp*2][1], blr[jp*2+1][0], blr[jp*2+1][1], wLb + eo);
            }
            #pragma unroll
            for (int i = 0; i < 4; i++)
                #pragma unroll
                for (int j = 0; j < 4; j++) {
                    mma16(acc[i][j], ahr[i][0], ahr[i][1], ahr[i][2], ahr[i][3], bhr[j][0], bhr[j][1]);
                    mma16(acc[i][j], ahr[i][0], ahr[i][1], ahr[i][2], ahr[i][3], blr[j][0], blr[j][1]);
                    mma16(acc[i][j], alr[i][0], alr[i][1], alr[i][2], alr[i][3], bhr[j][0], bhr[j][1]);
                }
        }
        __syncthreads();
    }

    float* Tout = g_T + (size_t)tt * NCODES * HID;
    #pragma unroll
    for (int j = 0; j < 4; j++) {
        const int col = n0 + nw + j * 8 + tq * 2;
        #pragma unroll
        for (int i = 0; i < 4; i++) {
            const int r = m0 + mw + i * 16 + g;
            *(float2*)&Tout[(size_t)r * HID + col]       = make_float2(acc[i][j][0], acc[i][j][1]);
            *(float2*)&Tout[(size_t)(r + 8) * HID + col] = make_float2(acc[i][j][2], acc[i][j][3]);
        }
    }
}

// =========================================================================
// gather-sum: h3[b] = gelu( sum_t T[t][idx[b,t]] + db1 )  -> split planes
// =========================================================================
__global__ __launch_bounds__(256)
void gather_sum(const float* __restrict__ db1,
                __nv_bfloat16* __restrict__ h3h, __nv_bfloat16* __restrict__ h3l)
{
    __shared__ int sidx[16];
    const int b = blockIdx.x;
    const int tid = threadIdx.x;
    if (tid < 16) sidx[tid] = g_idx[b * 16 + tid];
    __syncthreads();
    #pragma unroll
    for (int h = 0; h < 2; h++) {
        const int c = h * 256 + tid;
        float acc = 0.f;
        #pragma unroll
        for (int t = 0; t < 16; t++)
            acc += g_T[((size_t)t * NCODES + sidx[t]) * HID + c];
        float v = gelu_exact(acc + db1[c]);
        __nv_bfloat16 hh = __float2bfloat16(v);
        h3h[(size_t)b * HID + c] = hh;
        h3l[(size_t)b * HID + c] = __float2bfloat16(v - __bfloat162float(hh));
    }
}

// =========================================================================
// VQ (round-6 config; q writes removed)
// =========================================================================
#define ZPS 17408            // 128*136
#define VQ_SMEM (((size_t)6 * ZPS) * 2 + NCODES * 4)

__global__ __launch_bounds__(256, 1)
void vq_kernel(const __nv_bfloat16* __restrict__ zh, const __nv_bfloat16* __restrict__ zl,
               const __nv_bfloat16* __restrict__ cbh, const __nv_bfloat16* __restrict__ cbl,
               const float* __restrict__ cb)
{
    extern __shared__ __align__(16) char smraw[];
    __nv_bfloat16* sm  = (__nv_bfloat16*)smraw;
    __nv_bfloat16* ZsH = sm;
    __nv_bfloat16* ZsL = sm + ZPS;
    __nv_bfloat16* Cb  = sm + 2 * ZPS;
    float* cn = (float*)(sm + 6 * ZPS);
    const unsigned smu = (unsigned)__cvta_generic_to_shared(sm);

    __shared__ float red_d[128][4];
    __shared__ int   red_i[128][4];
    __shared__ int   best_idx[128];
    __shared__ float warp_sum[8];

    const int tid = threadIdx.x;
    const int t0  = blockIdx.x * 128;
    const int warp = tid >> 5, lane = tid & 31;
    const int mw = (warp & 1) * 64;
    const int nw = (warp >> 1) * 32;
    const int g  = lane >> 2;
    const int tq = lane & 3;

    const int lmr = lane & 15, lmk = (lane >> 4) * 8;
    const int brow = ((lane >> 4) << 3) + (lane & 7);
    const int bk8  = ((lane >> 3) & 1) << 3;

    *(float4*)&cn[tid * 4] = *(const float4*)&g_cnorm[tid * 4];

    #pragma unroll
    for (int l = 0; l < 8; l++) {
        int idx = l * 256 + tid;
        int row = idx >> 4, c16 = (idx & 15) * 8;
        cpa16(ZsH + row * 136 + c16, zh + (size_t)(t0 + row) * EMBED + c16);
        cpa16(ZsL + row * 136 + c16, zl + (size_t)(t0 + row) * EMBED + c16);
        cpa16(Cb + row * 136 + c16,        cbh + (size_t)row * EMBED + c16);
        cpa16(Cb + ZPS + row * 136 + c16,  cbl + (size_t)row * EMBED + c16);
    }
    CPA_COMMIT();
    CPA_WAIT0();
    __syncthreads();

    float bestD[8];
    int   bestI[8];
    #pragma unroll
    for (int s = 0; s < 8; s++) { bestD[s] = 3.4e38f; bestI[s] = 0; }

    for (int ct = 0; ct < 8; ct++) {
        const int cur = ct & 1, nxt = cur ^ 1;
        const unsigned cHb = smu + (unsigned)(2 * ZPS + cur * 2 * ZPS) * 2;
        const unsigned cLb = cHb + (unsigned)ZPS * 2;

        if (ct < 7) {
            const int c0n = (ct + 1) * 128;
            __nv_bfloat16* dH = Cb + nxt * 2 * ZPS;
            __nv_bfloat16* dL = dH + ZPS;
            #pragma unroll
            for (int l = 0; l < 8; l++) {
                int idx = l * 256 + tid;
                int row = idx >> 4, c16 = (idx & 15) * 8;
                cpa16(dH + row * 136 + c16, cbh + (size_t)(c0n + row) * EMBED + c16);
                cpa16(dL + row * 136 + c16, cbl + (size_t)(c0n + row) * EMBED + c16);
            }
            CPA_COMMIT();
        }

        float acc[4][4][4] = {};
        #pragma unroll
        for (int kt = 0; kt < 8; kt++) {
            const int kb = kt * 16;
            unsigned ahr[4][4], alr[4][4];
            #pragma unroll
            for (int i = 0; i < 4; i++) {
                const unsigned eo = (unsigned)((mw + i * 16 + lmr) * 136 + kb + lmk) * 2;
                ldm4(ahr[i][0], ahr[i][1], ahr[i][2], ahr[i][3], smu + eo);
                ldm4(alr[i][0], alr[i][1], alr[i][2], alr[i][3], smu + (unsigned)ZPS * 2 + eo);
            }
            unsigned bhr[4][2], blr[4][2];
            #pragma unroll
            for (int jp = 0; jp < 2; jp++) {
                const unsigned eo = (unsigned)((nw + jp * 16 + brow) * 136 + kb + bk8) * 2;
                ldm4(bhr[jp*2][0], bhr[jp*2][1], bhr[jp*2+1][0], bhr[jp*2+1][1], cHb + eo);
                ldm4(blr[jp*2][0], blr[jp*2][1], blr[jp*2+1][0], blr[jp*2+1][1], cLb + eo);
            }
            #pragma unroll
            for (int i = 0; i < 4; i++)
                #pragma unroll
                for (int j = 0; j < 4; j++) {
                    mma16(acc[i][j], ahr[i][0], ahr[i][1], ahr[i][2], ahr[i][3], bhr[j][0], bhr[j][1]);
                    mma16(acc[i][j], ahr[i][0], ahr[i][1], ahr[i][2], ahr[i][3], blr[j][0], blr[j][1]);
                    mma16(acc[i][j], alr[i][0], alr[i][1], alr[i][2], alr[i][3], bhr[j][0], bhr[j][1]);
                }
        }

        const int c0 = ct * 128;
        #pragma unroll
        for (int j = 0; j < 4; j++) {
            const int cbase = c0 + nw + j * 8 + tq * 2;
            const float cn0 = cn[cbase], cn1 = cn[cbase + 1];
            #pragma unroll
            for (int i = 0; i < 4; i++) {
                #pragma unroll
                for (int h = 0; h < 2; h++) {
                    const int s = i * 2 + h;
                    float d0 = fmaf(-2.0f, acc[i][j][h * 2 + 0], cn0);
                    float d1 = fmaf(-2.0f, acc[i][j][h * 2 + 1], cn1);
                    if (d0 < bestD[s] || (d0 == bestD[s] && cbase < bestI[s])) { bestD[s] = d0; bestI[s] = cbase; }
                    if (d1 < bestD[s] || (d1 == bestD[s] && cbase + 1 < bestI[s])) { bestD[s] = d1; bestI[s] = cbase + 1; }
                }
            }
        }

        if (ct < 7) {
            CPA_WAIT0();
            __syncthreads();
        }
    }

    #pragma unroll
    for (int s = 0; s < 8; s++) {
        #pragma unroll
        for (int o = 1; o < 4; o <<= 1) {
            float od = __shfl_xor_sync(0xFFFFFFFFu, bestD[s], o);
            int   oi = __shfl_xor_sync(0xFFFFFFFFu, bestI[s], o);
            if (od < bestD[s] || (od == bestD[s] && oi < bestI[s])) { bestD[s] = od; bestI[s] = oi; }
        }
    }
    if (tq == 0) {
        #pragma unroll
        for (int s = 0; s < 8; s++) {
            const int row = mw + (s >> 1) * 16 + (s & 1) * 8 + g;
            red_d[row][warp >> 1] = bestD[s];
            red_i[row][warp >> 1] = bestI[s];
        }
    }
    __syncthreads();
    if (tid < 128) {
        float bd = red_d[tid][0];
        int   bi = red_i[tid][0];
        #pragma unroll
        for (int x = 1; x < 4; x++) {
            float d = red_d[tid][x];
            int   c = red_i[tid][x];
            if (d < bd || (d == bd && c < bi)) { bd = d; bi = c; }
        }
        best_idx[tid] = bi;
        g_idx[t0 + tid] = bi;
    }
    __syncthreads();

    // commit loss (no q writes anymore)
    float lsum = 0.f;
    #pragma unroll 4
    for (int l = 0; l < 64; l++) {
        int e = l * 256 + tid;
        int trow = e >> 7;
        int d    = e & 127;
        int c    = best_idx[trow];
        float zv = __bfloat162float(ZsH[trow * 136 + d]) + __bfloat162float(ZsL[trow * 136 + d]);
        float diff = cb[(size_t)c * EMBED + d] - zv;
        lsum = fmaf(diff, diff, lsum);
    }
    #pragma unroll
    for (int o = 16; o > 0; o >>= 1) lsum += __shfl_down_sync(0xFFFFFFFFu, lsum, o);
    if (lane == 0) warp_sum[warp] = lsum;
    __syncthreads();
    if (tid == 0) {
        float s = 0.f;
        #pragma unroll
        for (int w = 0; w < 8; w++) s += warp_sum[w];
        atomicAdd(&g_loss, (double)s);
    }
}

// ------------------------- tail outputs -------------------------
__global__ void finalize_kernel(float* __restrict__ out)
{
    int i = blockIdx.x * 256 + threadIdx.x;
    if (i < NTOKENS_TOTAL) out[REC_ELEMS + i] = (float)g_idx[i];
    if (i == 0) out[REC_ELEMS + NTOKENS_TOTAL] = (float)(g_loss / (double)QELEMS);
}

// ------------------------- launch -------------------------
extern "C" void kernel_launch(void* const* d_in, const int* in_sizes, int n_in,
                              void* d_out, int out_size)
{
    const float* x   = (const float*)d_in[0];
    const float* eW1 = (const float*)d_in[1];
    const float* eb1 = (const float*)d_in[2];
    const float* eW2 = (const float*)d_in[3];
    const float* eb2 = (const float*)d_in[4];
    const float* eW3 = (const float*)d_in[5];
    const float* eb3 = (const float*)d_in[6];
    const float* dW1 = (const float*)d_in[7];
    const float* db1 = (const float*)d_in[8];
    const float* dW2 = (const float*)d_in[9];
    const float* db2 = (const float*)d_in[10];
    const float* dW3 = (const float*)d_in[11];
    const float* db3 = (const float*)d_in[12];
    const float* cb  = (const float*)d_in[13];
    float* out = (float*)d_out;

    __nv_bfloat16 *xh, *xl, *h1h, *h1l, *h2h, *h2l, *zh, *zl;
    __nv_bfloat16 *h3h, *h3l, *h4h, *h4l, *wh, *wl;
    cudaGetSymbolAddress((void**)&xh,  g_xh);
    cudaGetSymbolAddress((void**)&xl,  g_xl);
    cudaGetSymbolAddress((void**)&h1h, g_h1h);
    cudaGetSymbolAddress((void**)&h1l, g_h1l);
    cudaGetSymbolAddress((void**)&h2h, g_h2h);
    cudaGetSymbolAddress((void**)&h2l, g_h2l);
    cudaGetSymbolAddress((void**)&zh,  g_zh);
    cudaGetSymbolAddress((void**)&zl,  g_zl);
    cudaGetSymbolAddress((void**)&h3h, g_h3h);
    cudaGetSymbolAddress((void**)&h3l, g_h3l);
    cudaGetSymbolAddress((void**)&h4h, g_h4h);
    cudaGetSymbolAddress((void**)&h4l, g_h4l);
    cudaGetSymbolAddress((void**)&wh,  g_wh);
    cudaGetSymbolAddress((void**)&wl,  g_wl);

    cudaFuncSetAttribute(gemm_bf<1, 1>, cudaFuncAttributeMaxDynamicSharedMemorySize, GEMM_SMEM);
    cudaFuncSetAttribute(gemm_bf<0, 1>, cudaFuncAttributeMaxDynamicSharedMemorySize, GEMM_SMEM);
    cudaFuncSetAttribute(gemm_bf<0, 0>, cudaFuncAttributeMaxDynamicSharedMemorySize, GEMM_SMEM);
    cudaFuncSetAttribute(gemm_tab, cudaFuncAttributeMaxDynamicSharedMemorySize, GEMM_SMEM);
    cudaFuncSetAttribute(vq_kernel, cudaFuncAttributeMaxDynamicSharedMemorySize, (int)VQ_SMEM);

    code_norm_kernel<<<4, 256>>>(cb);
    pack_all<<<(X4 + CB4) / 256, 256>>>(x, cb, xh, xl, wh + OFF_CB, wl + OFF_CB);
    packT_all<<<3584, dim3(32, 8)>>>(eW1, eW2, eW3, dW1, dW2, dW3, wh, wl);

    // code table (independent of encoder; same stream)
    gemm_tab<<<dim3(HID / 128, NCODES / 128, NTOK), 256, GEMM_SMEM>>>(
        wh + OFF_CB, wl + OFF_CB, wh + OFF_DW1, wl + OFF_DW1);

    // encoder
    gemm_bf<1, 1><<<dim3(HID / 128,    NB / 128), 256, GEMM_SMEM>>>(
        xh, xl, wh + OFF_EW1, wl + OFF_EW1, eb1, nullptr, h1h, h1l, NB, IN_DIM, HID);
    gemm_bf<1, 1><<<dim3(HID / 128,    NB / 128), 256, GEMM_SMEM>>>(
        h1h, h1l, wh + OFF_EW2, wl + OFF_EW2, eb2, nullptr, h2h, h2l, NB, HID, HID);
    gemm_bf<0, 1><<<dim3(LATENT / 128, NB / 128), 256, GEMM_SMEM>>>(
        h2h, h2l, wh + OFF_EW3, wl + OFF_EW3, eb3, nullptr, zh, zl, NB, HID, LATENT);

    // VQ (indices + loss only)
    vq_kernel<<<NTOKENS_TOTAL / 128, 256, VQ_SMEM>>>(
        zh, zl, wh + OFF_CB, wl + OFF_CB, cb);

    // dec1 via gathered code table
    gather_sum<<<NB, 256>>>(db1, h3h, h3l);

    // dec2, dec3
    gemm_bf<1, 1><<<dim3(HID / 128,    NB / 128), 256, GEMM_SMEM>>>(
        h3h, h3l, wh + OFF_DW2, wl + OFF_DW2, db2, nullptr, h4h, h4l, NB, HID, HID);
    gemm_bf<0, 0><<<dim3(IN_DIM / 128, NB / 128), 256, GEMM_SMEM>>>(
        h4h, h4l, wh + OFF_DW3, wl + OFF_DW3, db3, out, nullptr, nullptr, NB, HID, IN_DIM);

    if (out_size >= REC_ELEMS + NTOKENS_TOTAL + 1)
        finalize_kernel<<<(NTOKENS_TOTAL + 255) / 256, 256>>>(out);
}

// round 10
// speedup vs baseline: 1.1239x; 1.0315x over previous
#include <cuda_runtime.h>
#include <cuda_bf16.h>
#include <math.h>

#define NB 4096
#define IN_DIM 1024
#define HID 512
#define EMBED 128
#define NTOK 16
#define NCODES 1024
#define LATENT 2048
#define NTOKENS_TOTAL (NB * NTOK)          // 65536
#define QELEMS (NTOKENS_TOTAL * EMBED)     // 8388608
#define REC_ELEMS (NB * IN_DIM)            // 4194304

// weight pool offsets (elements) — transposed [N][K] layouts
#define OFF_EW1 0
#define OFF_EW2 524288
#define OFF_EW3 786432
#define OFF_DW1 1835008
#define OFF_DW2 2883584
#define OFF_DW3 3145728
#define OFF_CB  3670016
#define WPOOL_N 3801088

// ------------------------- streams/events (created once at load) -------------------------
struct GraphCtx {
    cudaStream_t s2;
    cudaEvent_t ev0, evA, evB, evT, evV, evF;
    GraphCtx() {
        cudaStreamCreateWithFlags(&s2, cudaStreamNonBlocking);
        cudaEventCreateWithFlags(&ev0, cudaEventDisableTiming);
        cudaEventCreateWithFlags(&evA, cudaEventDisableTiming);
        cudaEventCreateWithFlags(&evB, cudaEventDisableTiming);
        cudaEventCreateWithFlags(&evT, cudaEventDisableTiming);
        cudaEventCreateWithFlags(&evV, cudaEventDisableTiming);
        cudaEventCreateWithFlags(&evF, cudaEventDisableTiming);
    }
};
static GraphCtx g_ctx;

// ------------------------- scratch -------------------------
__device__ __nv_bfloat16 g_xh[NB * IN_DIM];
__device__ __nv_bfloat16 g_xl[NB * IN_DIM];
__device__ __nv_bfloat16 g_h1h[NB * HID];
__device__ __nv_bfloat16 g_h1l[NB * HID];
__device__ __nv_bfloat16 g_h2h[NB * HID];
__device__ __nv_bfloat16 g_h2l[NB * HID];
__device__ __nv_bfloat16 g_zh[NB * LATENT];
__device__ __nv_bfloat16 g_zl[NB * LATENT];
__device__ __nv_bfloat16 g_h3h[NB * HID];
__device__ __nv_bfloat16 g_h3l[NB * HID];
__device__ __nv_bfloat16 g_h4h[NB * HID];
__device__ __nv_bfloat16 g_h4l[NB * HID];
__device__ __nv_bfloat16 g_wh[WPOOL_N];
__device__ __nv_bfloat16 g_wl[WPOOL_N];
__device__ float  g_T[NTOK * NCODES * HID];   // 33.5 MB code table
__device__ float  g_cnorm[NCODES];
__device__ int    g_idx[NTOKENS_TOTAL];
__device__ double g_loss;

__device__ __forceinline__ float gelu_exact(float x) {
    return 0.5f * x * (1.0f + erff(x * 0.70710678118654752440f));
}

__device__ __forceinline__ void mma16(float* d,
                                      unsigned a0, unsigned a1, unsigned a2, unsigned a3,
                                      unsigned b0, unsigned b1) {
    asm volatile(
        "mma.sync.aligned.m16n8k16.row.col.f32.bf16.bf16.f32 "
        "{%0,%1,%2,%3},{%4,%5,%6,%7},{%8,%9},{%0,%1,%2,%3};"
        : "+f"(d[0]), "+f"(d[1]), "+f"(d[2]), "+f"(d[3])
        : "r"(a0), "r"(a1), "r"(a2), "r"(a3), "r"(b0), "r"(b1));
}

__device__ __forceinline__ void ldm4(unsigned &r0, unsigned &r1, unsigned &r2, unsigned &r3,
                                     unsigned addr) {
    asm volatile("ldmatrix.sync.aligned.m8n8.x4.shared.b16 {%0,%1,%2,%3}, [%4];"
                 : "=r"(r0), "=r"(r1), "=r"(r2), "=r"(r3) : "r"(addr));
}

__device__ __forceinline__ void cpa16(__nv_bfloat16* dst, const __nv_bfloat16* src) {
    unsigned a = (unsigned)__cvta_generic_to_shared(dst);
    asm volatile("cp.async.cg.shared.global [%0], [%1], 16;" :: "r"(a), "l"(src));
}
__device__ __forceinline__ void cpa16u(unsigned dst, const __nv_bfloat16* src) {
    asm volatile("cp.async.cg.shared.global [%0], [%1], 16;" :: "r"(dst), "l"(src));
}
#define CPA_COMMIT() asm volatile("cp.async.commit_group;")
#define CPA_WAIT0()  asm volatile("cp.async.wait_group 0;")
#define CPA_WAIT1()  asm volatile("cp.async.wait_group 1;")

// ------------------------- prep kernels -------------------------
__device__ __forceinline__ void split_f4(float4 v, __nv_bfloat16* hi, __nv_bfloat16* lo, int i) {
    __nv_bfloat16 h0 = __float2bfloat16(v.x);
    __nv_bfloat16 h1 = __float2bfloat16(v.y);
    __nv_bfloat16 h2 = __float2bfloat16(v.z);
    __nv_bfloat16 h3 = __float2bfloat16(v.w);
    __nv_bfloat162 hh0; hh0.x = h0; hh0.y = h1;
    __nv_bfloat162 hh1; hh1.x = h2; hh1.y = h3;
    __nv_bfloat162 ll0;
    ll0.x = __float2bfloat16(v.x - __bfloat162float(h0));
    ll0.y = __float2bfloat16(v.y - __bfloat162float(h1));
    __nv_bfloat162 ll1;
    ll1.x = __float2bfloat16(v.z - __bfloat162float(h2));
    ll1.y = __float2bfloat16(v.w - __bfloat162float(h3));
    ((__nv_bfloat162*)hi)[i * 2]     = hh0;
    ((__nv_bfloat162*)hi)[i * 2 + 1] = hh1;
    ((__nv_bfloat162*)lo)[i * 2]     = ll0;
    ((__nv_bfloat162*)lo)[i * 2 + 1] = ll1;
}

#define X4  (NB * IN_DIM / 4)       // 1048576
#define CB4 (NCODES * EMBED / 4)    // 32768

__global__ void pack_all(const float* __restrict__ x, const float* __restrict__ cb,
                         __nv_bfloat16* __restrict__ xh, __nv_bfloat16* __restrict__ xl,
                         __nv_bfloat16* __restrict__ ch, __nv_bfloat16* __restrict__ cl)
{
    int i = blockIdx.x * blockDim.x + threadIdx.x;
    if (i < X4) {
        split_f4(((const float4*)x)[i], xh, xl, i);
    } else if (i < X4 + CB4) {
        int j = i - X4;
        split_f4(((const float4*)cb)[j], ch, cl, j);
    }
}

__global__ void packT_all(const float* __restrict__ eW1, const float* __restrict__ eW2,
                          const float* __restrict__ eW3, const float* __restrict__ dW1,
                          const float* __restrict__ dW2, const float* __restrict__ dW3)
{
    __shared__ float t[32][33];
    int bid = blockIdx.x;
    const float* W; int K, N, off, lt;
    if      (bid < 512)  { W = eW1; K = IN_DIM; N = HID;    off = OFF_EW1; lt = bid; }
    else if (bid < 768)  { W = eW2; K = HID;    N = HID;    off = OFF_EW2; lt = bid - 512; }
    else if (bid < 1792) { W = eW3; K = HID;    N = LATENT; off = OFF_EW3; lt = bid - 768; }
    else if (bid < 2816) { W = dW1; K = LATENT; N = HID;    off = OFF_DW1; lt = bid - 1792; }
    else if (bid < 3072) { W = dW2; K = HID;    N = HID;    off = OFF_DW2; lt = bid - 2816; }
    else                 { W = dW3; K = HID;    N = IN_DIM; off = OFF_DW3; lt = bid - 3072; }
    const int ntn = N >> 5;
    const int n0 = (lt % ntn) * 32, k0 = (lt / ntn) * 32;
    const int tx = threadIdx.x, ty = threadIdx.y;
    #pragma unroll
    for (int r = 0; r < 32; r += 8)
        t[ty + r][tx] = W[(size_t)(k0 + ty + r) * N + n0 + tx];
    __syncthreads();
    #pragma unroll
    for (int r = 0; r < 32; r += 8) {
        float v = t[tx][ty + r];
        size_t o = (size_t)off + (size_t)(n0 + ty + r) * K + k0 + tx;
        __nv_bfloat16 h = __float2bfloat16(v);
        g_wh[o] = h;
        g_wl[o] = __float2bfloat16(v - __bfloat162float(h));
    }
}

__global__ void code_norm_kernel(const float* __restrict__ cb) {
    int c = blockIdx.x * blockDim.x + threadIdx.x;
    if (c == 0) g_loss = 0.0;
    if (c < NCODES) {
        float s = 0.f;
        #pragma unroll 4
        for (int d = 0; d < EMBED; d++) {
            float v = cb[c * EMBED + d];
            s = fmaf(v, v, s);
        }
        g_cnorm[c] = s;
    }
}

// =========================================================================
// bf16 3-term GEMM, cp.async 3-stage, 256 thr (8 warps 2x4), ldmatrix.
// =========================================================================
#define GPLANE 5120                  // 128*40 elems
#define GSTAGE (4 * GPLANE)          // 20480 elems
#define GEMM_SMEM (3 * GSTAGE * 2)   // 122880 bytes

template <int ACT, int SPLIT>
__global__ __launch_bounds__(256, 1)
void gemm_bf(const __nv_bfloat16* __restrict__ Ah, const __nv_bfloat16* __restrict__ Al,
             const __nv_bfloat16* __restrict__ Wh, const __nv_bfloat16* __restrict__ Wl,
             const float* __restrict__ bias,
             float* __restrict__ C,
             __nv_bfloat16* __restrict__ Ch, __nv_bfloat16* __restrict__ Cl,
             int M, int K, int N)
{
    extern __shared__ __align__(16) char smraw[];
    const unsigned smu = (unsigned)__cvta_generic_to_shared(smraw);

    const int tid  = threadIdx.x;
    const int m0   = blockIdx.y * 128;
    const int n0   = blockIdx.x * 128;
    const int warp = tid >> 5, lane = tid & 31;
    const int mw = (warp & 1) * 64;
    const int nw = (warp >> 1) * 32;
    const int g  = lane >> 2;
    const int tq = lane & 3;

    const int lmr = lane & 15, lmk = (lane >> 4) * 8;
    const int brow = ((lane >> 4) << 3) + (lane & 7);
    const int bk8  = ((lane >> 3) & 1) << 3;

    const __nv_bfloat16* sp0 = Ah + (size_t)m0 * K;
    const __nv_bfloat16* sp1 = Al + (size_t)m0 * K;
    const __nv_bfloat16* sp2 = Wh + (size_t)n0 * K;
    const __nv_bfloat16* sp3 = Wl + (size_t)n0 * K;

    const int KT = K >> 5;

    auto fill = [&](int kt, int s) {
        const __nv_bfloat16* sp[4] = { sp0 + kt * 32, sp1 + kt * 32, sp2 + kt * 32, sp3 + kt * 32 };
        #pragma unroll
        for (int l = 0; l < 8; l++) {
            int c = l * 256 + tid;
            int p = c >> 9;
            int r = (c >> 2) & 127;
            int q = c & 3;
            cpa16u(smu + (unsigned)(s * GSTAGE + p * GPLANE + r * 40 + q * 8) * 2,
                   sp[p] + (size_t)r * K + q * 8);
        }
        CPA_COMMIT();
    };

    fill(0, 0);
    fill(1, 1);

    float acc[4][4][4] = {};

    for (int kt = 0; kt < KT; kt++) {
        if (kt + 1 < KT) { CPA_WAIT1(); } else { CPA_WAIT0(); }
        __syncthreads();
        if (kt + 2 < KT) fill(kt + 2, (kt + 2) % 3);

        const int s = kt % 3;
        const unsigned aHb = smu + (unsigned)(s * GSTAGE) * 2;
        const unsigned aLb = aHb + (unsigned)GPLANE * 2;
        const unsigned wHb = aLb + (unsigned)GPLANE * 2;
        const unsigned wLb = wHb + (unsigned)GPLANE * 2;
        #pragma unroll
        for (int ks = 0; ks < 32; ks += 16) {
            unsigned ahr[4][4], alr[4][4];
            #pragma unroll
            for (int i = 0; i < 4; i++) {
                const unsigned eo = (unsigned)((mw + i * 16 + lmr) * 40 + ks + lmk) * 2;
                ldm4(ahr[i][0], ahr[i][1], ahr[i][2], ahr[i][3], aHb + eo);
                ldm4(alr[i][0], alr[i][1], alr[i][2], alr[i][3], aLb + eo);
            }
            unsigned bhr[4][2], blr[4][2];
            #pragma unroll
            for (int jp = 0; jp < 2; jp++) {
                const unsigned eo = (unsigned)((nw + jp * 16 + brow) * 40 + ks + bk8) * 2;
                ldm4(bhr[jp*2][0], bhr[jp*2][1], bhr[jp*2+1][0], bhr[jp*2+1][1], wHb + eo);
                ldm4(blr[jp*2][0], blr[jp*2][1], blr[jp*2+1][0], blr[jp*2+1][1], wLb + eo);
            }
            #pragma unroll
            for (int i = 0; i < 4; i++)
                #pragma unroll
                for (int j = 0; j < 4; j++) {
                    mma16(acc[i][j], ahr[i][0], ahr[i][1], ahr[i][2], ahr[i][3], bhr[j][0], bhr[j][1]);
                    mma16(acc[i][j], ahr[i][0], ahr[i][1], ahr[i][2], ahr[i][3], blr[j][0], blr[j][1]);
                    mma16(acc[i][j], alr[i][0], alr[i][1], alr[i][2], alr[i][3], bhr[j][0], bhr[j][1]);
                }
        }
        __syncthreads();
    }

    #pragma unroll
    for (int j = 0; j < 4; j++) {
        const int col = n0 + nw + j * 8 + tq * 2;
        const float b0 = bias[col], b1 = bias[col + 1];
        #pragma unroll
        for (int i = 0; i < 4; i++) {
            const int r = m0 + mw + i * 16 + g;
            float v0 = acc[i][j][0] + b0;
            float v1 = acc[i][j][1] + b1;
            float v2 = acc[i][j][2] + b0;
            float v3 = acc[i][j][3] + b1;
            if (ACT) { v0 = gelu_exact(v0); v1 = gelu_exact(v1); v2 = gelu_exact(v2); v3 = gelu_exact(v3); }
            const size_t o0 = (size_t)r * N + col;
            const size_t o1 = (size_t)(r + 8) * N + col;
            if (SPLIT) {
                __nv_bfloat16 h0 = __float2bfloat16(v0), h1 = __float2bfloat16(v1);
                __nv_bfloat16 h2 = __float2bfloat16(v2), h3 = __float2bfloat16(v3);
                __nv_bfloat162 hh0; hh0.x = h0; hh0.y = h1;
                __nv_bfloat162 hh1; hh1.x = h2; hh1.y = h3;
                __nv_bfloat162 ll0;
                ll0.x = __float2bfloat16(v0 - __bfloat162float(h0));
                ll0.y = __float2bfloat16(v1 - __bfloat162float(h1));
                __nv_bfloat162 ll1;
                ll1.x = __float2bfloat16(v2 - __bfloat162float(h2));
                ll1.y = __float2bfloat16(v3 - __bfloat162float(h3));
                *(__nv_bfloat162*)&Ch[o0] = hh0;
                *(__nv_bfloat162*)&Ch[o1] = hh1;
                *(__nv_bfloat162*)&Cl[o0] = ll0;
                *(__nv_bfloat162*)&Cl[o1] = ll1;
            } else {
                *(float2*)&C[o0] = make_float2(v0, v1);
                *(float2*)&C[o1] = make_float2(v2, v3);
            }
        }
    }
}

// =========================================================================
// Code table: T[t][c][n] = cb[c] @ dW1[t*128:(t+1)*128, n]
// =========================================================================
__global__ __launch_bounds__(256, 1)
void gemm_tab(const __nv_bfloat16* __restrict__ Ah, const __nv_bfloat16* __restrict__ Al,
              const __nv_bfloat16* __restrict__ Wh, const __nv_bfloat16* __restrict__ Wl)
{
    extern __shared__ __align__(16) char smraw[];
    const unsigned smu = (unsigned)__cvta_generic_to_shared(smraw);

    const int tid  = threadIdx.x;
    const int m0   = blockIdx.y * 128;
    const int n0   = blockIdx.x * 128;
    const int tt   = blockIdx.z;
    const int warp = tid >> 5, lane = tid & 31;
    const int mw = (warp & 1) * 64;
    const int nw = (warp >> 1) * 32;
    const int g  = lane >> 2;
    const int tq = lane & 3;

    const int lmr = lane & 15, lmk = (lane >> 4) * 8;
    const int brow = ((lane >> 4) << 3) + (lane & 7);
    const int bk8  = ((lane >> 3) & 1) << 3;

    const int AK = EMBED;
    const int WK = LATENT;
    const int koff = tt * EMBED;

    const __nv_bfloat16* sp0 = Ah + (size_t)m0 * AK;
    const __nv_bfloat16* sp1 = Al + (size_t)m0 * AK;
    const __nv_bfloat16* sp2 = Wh + (size_t)n0 * WK + koff;
    const __nv_bfloat16* sp3 = Wl + (size_t)n0 * WK + koff;

    const int KT = 4;

    auto fill = [&](int kt, int s) {
        #pragma unroll
        for (int l = 0; l < 8; l++) {
            int c = l * 256 + tid;
            int p = c >> 9;
            int r = (c >> 2) & 127;
            int q = c & 3;
            const __nv_bfloat16* src;
            if (p == 0)      src = sp0 + (size_t)r * AK;
            else if (p == 1) src = sp1 + (size_t)r * AK;
            else if (p == 2) src = sp2 + (size_t)r * WK;
            else             src = sp3 + (size_t)r * WK;
            cpa16u(smu + (unsigned)(s * GSTAGE + p * GPLANE + r * 40 + q * 8) * 2,
                   src + kt * 32 + q * 8);
        }
        CPA_COMMIT();
    };

    fill(0, 0);
    fill(1, 1);

    float acc[4][4][4] = {};

    for (int kt = 0; kt < KT; kt++) {
        if (kt + 1 < KT) { CPA_WAIT1(); } else { CPA_WAIT0(); }
        __syncthreads();
        if (kt + 2 < KT) fill(kt + 2, (kt + 2) % 3);

        const int s = kt % 3;
        const unsigned aHb = smu + (unsigned)(s * GSTAGE) * 2;
        const unsigned aLb = aHb + (unsigned)GPLANE * 2;
        const unsigned wHb = aLb + (unsigned)GPLANE * 2;
        const unsigned wLb = wHb + (unsigned)GPLANE * 2;
        #pragma unroll
        for (int ks = 0; ks < 32; ks += 16) {
            unsigned ahr[4][4], alr[4][4];
            #pragma unroll
            for (int i = 0; i < 4; i++) {
                const unsigned eo = (unsigned)((mw + i * 16 + lmr) * 40 + ks + lmk) * 2;
                ldm4(ahr[i][0], ahr[i][1], ahr[i][2], ahr[i][3], aHb + eo);
                ldm4(alr[i][0], alr[i][1], alr[i][2], alr[i][3], aLb + eo);
            }
            unsigned bhr[4][2], blr[4][2];
            #pragma unroll
            for (int jp = 0; jp < 2; jp++) {
                const unsigned eo = (unsigned)((nw + jp * 16 + brow) * 40 + ks + bk8) * 2;
                ldm4(bhr[jp*2][0], bhr[jp*2][1], bhr[jp*2+1][0], bhr[jp*2+1][1], wHb + eo);
                ldm4(blr[jp*2][0], blr[jp*2][1], blr[jp*2+1][0], blr[jp*2+1][1], wLb + eo);
            }
            #pragma unroll
            for (int i = 0; i < 4; i++)
                #pragma unroll
                for (int j = 0; j < 4; j++) {
                    mma16(acc[i][j], ahr[i][0], ahr[i][1], ahr[i][2], ahr[i][3], bhr[j][0], bhr[j][1]);
                    mma16(acc[i][j], ahr[i][0], ahr[i][1], ahr[i][2], ahr[i][3], blr[j][0], blr[j][1]);
                    mma16(acc[i][j], alr[i][0], alr[i][1], alr[i][2], alr[i][3], bhr[j][0], bhr[j][1]);
                }
        }
        __syncthreads();
    }

    float* Tout = g_T + (size_t)tt * NCODES * HID;
    #pragma unroll
    for (int j = 0; j < 4; j++) {
        const int col = n0 + nw + j * 8 + tq * 2;
        #pragma unroll
        for (int i = 0; i < 4; i++) {
            const int r = m0 + mw + i * 16 + g;
            *(float2*)&Tout[(size_t)r * HID + col]       = make_float2(acc[i][j][0], acc[i][j][1]);
            *(float2*)&Tout[(size_t)(r + 8) * HID + col] = make_float2(acc[i][j][2], acc[i][j][3]);
        }
    }
}

// =========================================================================
// gather-sum: h3[b] = gelu( sum_t T[t][idx[b,t]] + db1 )
// =========================================================================
__global__ __launch_bounds__(256)
void gather_sum(const float* __restrict__ db1,
                __nv_bfloat16* __restrict__ h3h, __nv_bfloat16* __restrict__ h3l)
{
    __shared__ int sidx[16];
    const int b = blockIdx.x;
    const int tid = threadIdx.x;
    if (tid < 16) sidx[tid] = g_idx[b * 16 + tid];
    __syncthreads();
    #pragma unroll
    for (int h = 0; h < 2; h++) {
        const int c = h * 256 + tid;
        float acc = 0.f;
        #pragma unroll
        for (int t = 0; t < 16; t++)
            acc += g_T[((size_t)t * NCODES + sidx[t]) * HID + c];
        float v = gelu_exact(acc + db1[c]);
        __nv_bfloat16 hh = __float2bfloat16(v);
        h3h[(size_t)b * HID + c] = hh;
        h3l[(size_t)b * HID + c] = __float2bfloat16(v - __bfloat162float(hh));
    }
}

// =========================================================================
// VQ
// =========================================================================
#define ZPS 17408            // 128*136
#define VQ_SMEM (((size_t)6 * ZPS) * 2 + NCODES * 4)

__global__ __launch_bounds__(256, 1)
void vq_kernel(const __nv_bfloat16* __restrict__ zh, const __nv_bfloat16* __restrict__ zl,
               const __nv_bfloat16* __restrict__ cbh, const __nv_bfloat16* __restrict__ cbl,
               const float* __restrict__ cb)
{
    extern __shared__ __align__(16) char smraw[];
    __nv_bfloat16* sm  = (__nv_bfloat16*)smraw;
    __nv_bfloat16* ZsH = sm;
    __nv_bfloat16* ZsL = sm + ZPS;
    __nv_bfloat16* Cb  = sm + 2 * ZPS;
    float* cn = (float*)(sm + 6 * ZPS);
    const unsigned smu = (unsigned)__cvta_generic_to_shared(sm);

    __shared__ float red_d[128][4];
    __shared__ int   red_i[128][4];
    __shared__ int   best_idx[128];
    __shared__ float warp_sum[8];

    const int tid = threadIdx.x;
    const int t0  = blockIdx.x * 128;
    const int warp = tid >> 5, lane = tid & 31;
    const int mw = (warp & 1) * 64;
    const int nw = (warp >> 1) * 32;
    const int g  = lane >> 2;
    const int tq = lane & 3;

    const int lmr = lane & 15, lmk = (lane >> 4) * 8;
    const int brow = ((lane >> 4) << 3) + (lane & 7);
    const int bk8  = ((lane >> 3) & 1) << 3;

    *(float4*)&cn[tid * 4] = *(const float4*)&g_cnorm[tid * 4];

    #pragma unroll
    for (int l = 0; l < 8; l++) {
        int idx = l * 256 + tid;
        int row = idx >> 4, c16 = (idx & 15) * 8;
        cpa16(ZsH + row * 136 + c16, zh + (size_t)(t0 + row) * EMBED + c16);
        cpa16(ZsL + row * 136 + c16, zl + (size_t)(t0 + row) * EMBED + c16);
        cpa16(Cb + row * 136 + c16,        cbh + (size_t)row * EMBED + c16);
        cpa16(Cb + ZPS + row * 136 + c16,  cbl + (size_t)row * EMBED + c16);
    }
    CPA_COMMIT();
    CPA_WAIT0();
    __syncthreads();

    float bestD[8];
    int   bestI[8];
    #pragma unroll
    for (int s = 0; s < 8; s++) { bestD[s] = 3.4e38f; bestI[s] = 0; }

    for (int ct = 0; ct < 8; ct++) {
        const int cur = ct & 1, nxt = cur ^ 1;
        const unsigned cHb = smu + (unsigned)(2 * ZPS + cur * 2 * ZPS) * 2;
        const unsigned cLb = cHb + (unsigned)ZPS * 2;

        if (ct < 7) {
            const int c0n = (ct + 1) * 128;
            __nv_bfloat16* dH = Cb + nxt * 2 * ZPS;
            __nv_bfloat16* dL = dH + ZPS;
            #pragma unroll
            for (int l = 0; l < 8; l++) {
                int idx = l * 256 + tid;
                int row = idx >> 4, c16 = (idx & 15) * 8;
                cpa16(dH + row * 136 + c16, cbh + (size_t)(c0n + row) * EMBED + c16);
                cpa16(dL + row * 136 + c16, cbl + (size_t)(c0n + row) * EMBED + c16);
            }
            CPA_COMMIT();
        }

        float acc[4][4][4] = {};
        #pragma unroll
        for (int kt = 0; kt < 8; kt++) {
            const int kb = kt * 16;
            unsigned ahr[4][4], alr[4][4];
            #pragma unroll
            for (int i = 0; i < 4; i++) {
                const unsigned eo = (unsigned)((mw + i * 16 + lmr) * 136 + kb + lmk) * 2;
                ldm4(ahr[i][0], ahr[i][1], ahr[i][2], ahr[i][3], smu + eo);
                ldm4(alr[i][0], alr[i][1], alr[i][2], alr[i][3], smu + (unsigned)ZPS * 2 + eo);
            }
            unsigned bhr[4][2], blr[4][2];
            #pragma unroll
            for (int jp = 0; jp < 2; jp++) {
                const unsigned eo = (unsigned)((nw + jp * 16 + brow) * 136 + kb + bk8) * 2;
                ldm4(bhr[jp*2][0], bhr[jp*2][1], bhr[jp*2+1][0], bhr[jp*2+1][1], cHb + eo);
                ldm4(blr[jp*2][0], blr[jp*2][1], blr[jp*2+1][0], blr[jp*2+1][1], cLb + eo);
            }
            #pragma unroll
            for (int i = 0; i < 4; i++)
                #pragma unroll
                for (int j = 0; j < 4; j++) {
                    mma16(acc[i][j], ahr[i][0], ahr[i][1], ahr[i][2], ahr[i][3], bhr[j][0], bhr[j][1]);
                    mma16(acc[i][j], ahr[i][0], ahr[i][1], ahr[i][2], ahr[i][3], blr[j][0], blr[j][1]);
                    mma16(acc[i][j], alr[i][0], alr[i][1], alr[i][2], alr[i][3], bhr[j][0], bhr[j][1]);
                }
        }

        const int c0 = ct * 128;
        #pragma unroll
        for (int j = 0; j < 4; j++) {
            const int cbase = c0 + nw + j * 8 + tq * 2;
            const float cn0 = cn[cbase], cn1 = cn[cbase + 1];
            #pragma unroll
            for (int i = 0; i < 4; i++) {
                #pragma unroll
                for (int h = 0; h < 2; h++) {
                    const int s = i * 2 + h;
                    float d0 = fmaf(-2.0f, acc[i][j][h * 2 + 0], cn0);
                    float d1 = fmaf(-2.0f, acc[i][j][h * 2 + 1], cn1);
                    if (d0 < bestD[s] || (d0 == bestD[s] && cbase < bestI[s])) { bestD[s] = d0; bestI[s] = cbase; }
                    if (d1 < bestD[s] || (d1 == bestD[s] && cbase + 1 < bestI[s])) { bestD[s] = d1; bestI[s] = cbase + 1; }
                }
            }
        }

        if (ct < 7) {
            CPA_WAIT0();
            __syncthreads();
        }
    }

    #pragma unroll
    for (int s = 0; s < 8; s++) {
        #pragma unroll
        for (int o = 1; o < 4; o <<= 1) {
            float od = __shfl_xor_sync(0xFFFFFFFFu, bestD[s], o);
            int   oi = __shfl_xor_sync(0xFFFFFFFFu, bestI[s], o);
            if (od < bestD[s] || (od == bestD[s] && oi < bestI[s])) { bestD[s] = od; bestI[s] = oi; }
        }
    }
    if (tq == 0) {
        #pragma unroll
        for (int s = 0; s < 8; s++) {
            const int row = mw + (s >> 1) * 16 + (s & 1) * 8 + g;
            red_d[row][warp >> 1] = bestD[s];
            red_i[row][warp >> 1] = bestI[s];
        }
    }
    __syncthreads();
    if (tid < 128) {
        float bd = red_d[tid][0];
        int   bi = red_i[tid][0];
        #pragma unroll
        for (int x = 1; x < 4; x++) {
            float d = red_d[tid][x];
            int   c = red_i[tid][x];
            if (d < bd || (d == bd && c < bi)) { bd = d; bi = c; }
        }
        best_idx[tid] = bi;
        g_idx[t0 + tid] = bi;
    }
    __syncthreads();

    float lsum = 0.f;
    #pragma unroll 4
    for (int l = 0; l < 64; l++) {
        int e = l * 256 + tid;
        int trow = e >> 7;
        int d    = e & 127;
        int c    = best_idx[trow];
        float zv = __bfloat162float(ZsH[trow * 136 + d]) + __bfloat162float(ZsL[trow * 136 + d]);
        float diff = cb[(size_t)c * EMBED + d] - zv;
        lsum = fmaf(diff, diff, lsum);
    }
    #pragma unroll
    for (int o = 16; o > 0; o >>= 1) lsum += __shfl_down_sync(0xFFFFFFFFu, lsum, o);
    if (lane == 0) warp_sum[warp] = lsum;
    __syncthreads();
    if (tid == 0) {
        float s = 0.f;
        #pragma unroll
        for (int w = 0; w < 8; w++) s += warp_sum[w];
        atomicAdd(&g_loss, (double)s);
    }
}

// ------------------------- tail outputs -------------------------
__global__ void finalize_kernel(float* __restrict__ out)
{
    int i = blockIdx.x * 256 + threadIdx.x;
    if (i < NTOKENS_TOTAL) out[REC_ELEMS + i] = (float)g_idx[i];
    if (i == 0) out[REC_ELEMS + NTOKENS_TOTAL] = (float)(g_loss / (double)QELEMS);
}

// ------------------------- launch -------------------------
extern "C" void kernel_launch(void* const* d_in, const int* in_sizes, int n_in,
                              void* d_out, int out_size)
{
    const float* x   = (const float*)d_in[0];
    const float* eW1 = (const float*)d_in[1];
    const float* eb1 = (const float*)d_in[2];
    const float* eW2 = (const float*)d_in[3];
    const float* eb2 = (const float*)d_in[4];
    const float* eW3 = (const float*)d_in[5];
    const float* eb3 = (const float*)d_in[6];
    const float* dW1 = (const float*)d_in[7];
    const float* db1 = (const float*)d_in[8];
    const float* dW2 = (const float*)d_in[9];
    const float* db2 = (const float*)d_in[10];
    const float* dW3 = (const float*)d_in[11];
    const float* db3 = (const float*)d_in[12];
    const float* cb  = (const float*)d_in[13];
    float* out = (float*)d_out;

    __nv_bfloat16 *xh, *xl, *h1h, *h1l, *h2h, *h2l, *zh, *zl;
    __nv_bfloat16 *h3h, *h3l, *h4h, *h4l, *wh, *wl;
    cudaGetSymbolAddress((void**)&xh,  g_xh);
    cudaGetSymbolAddress((void**)&xl,  g_xl);
    cudaGetSymbolAddress((void**)&h1h, g_h1h);
    cudaGetSymbolAddress((void**)&h1l, g_h1l);
    cudaGetSymbolAddress((void**)&h2h, g_h2h);
    cudaGetSymbolAddress((void**)&h2l, g_h2l);
    cudaGetSymbolAddress((void**)&zh,  g_zh);
    cudaGetSymbolAddress((void**)&zl,  g_zl);
    cudaGetSymbolAddress((void**)&h3h, g_h3h);
    cudaGetSymbolAddress((void**)&h3l, g_h3l);
    cudaGetSymbolAddress((void**)&h4h, g_h4h);
    cudaGetSymbolAddress((void**)&h4l, g_h4l);
    cudaGetSymbolAddress((void**)&wh,  g_wh);
    cudaGetSymbolAddress((void**)&wl,  g_wl);

    cudaFuncSetAttribute(gemm_bf<1, 1>, cudaFuncAttributeMaxDynamicSharedMemorySize, GEMM_SMEM);
    cudaFuncSetAttribute(gemm_bf<0, 1>, cudaFuncAttributeMaxDynamicSharedMemorySize, GEMM_SMEM);
    cudaFuncSetAttribute(gemm_bf<0, 0>, cudaFuncAttributeMaxDynamicSharedMemorySize, GEMM_SMEM);
    cudaFuncSetAttribute(gemm_tab, cudaFuncAttributeMaxDynamicSharedMemorySize, GEMM_SMEM);
    cudaFuncSetAttribute(vq_kernel, cudaFuncAttributeMaxDynamicSharedMemorySize, (int)VQ_SMEM);

    cudaStream_t s2 = g_ctx.s2;

    // ---- fork: weights pack on s2, x/cb pack + norms on default ----
    cudaEventRecord(g_ctx.ev0, 0);
    cudaStreamWaitEvent(s2, g_ctx.ev0, 0);
    packT_all<<<3584, dim3(32, 8), 0, s2>>>(eW1, eW2, eW3, dW1, dW2, dW3);

    code_norm_kernel<<<4, 256>>>(cb);
    pack_all<<<(X4 + CB4) / 256, 256>>>(x, cb, xh, xl, wh + OFF_CB, wl + OFF_CB);

    // cross-sync: default needs weights; s2 needs cb planes
    cudaEventRecord(g_ctx.evA, 0);      // pack_all done (cb planes)
    cudaEventRecord(g_ctx.evB, s2);     // packT_all done (weights)
    cudaStreamWaitEvent(0, g_ctx.evB, 0);
    cudaStreamWaitEvent(s2, g_ctx.evA, 0);

    // branch B: code table on s2 (hidden under encoder)
    gemm_tab<<<dim3(HID / 128, NCODES / 128, NTOK), 256, GEMM_SMEM, s2>>>(
        wh + OFF_CB, wl + OFF_CB, wh + OFF_DW1, wl + OFF_DW1);

    // branch A: encoder + VQ on default
    gemm_bf<1, 1><<<dim3(HID / 128,    NB / 128), 256, GEMM_SMEM>>>(
        xh, xl, wh + OFF_EW1, wl + OFF_EW1, eb1, nullptr, h1h, h1l, NB, IN_DIM, HID);
    gemm_bf<1, 1><<<dim3(HID / 128,    NB / 128), 256, GEMM_SMEM>>>(
        h1h, h1l, wh + OFF_EW2, wl + OFF_EW2, eb2, nullptr, h2h, h2l, NB, HID, HID);
    gemm_bf<0, 1><<<dim3(LATENT / 128, NB / 128), 256, GEMM_SMEM>>>(
        h2h, h2l, wh + OFF_EW3, wl + OFF_EW3, eb3, nullptr, zh, zl, NB, HID, LATENT);

    vq_kernel<<<NTOKENS_TOTAL / 128, 256, VQ_SMEM>>>(
        zh, zl, wh + OFF_CB, wl + OFF_CB, cb);

    // finalize on s2 (needs VQ results; overlaps with gather/dec2)
    cudaEventRecord(g_ctx.evV, 0);      // VQ done
    cudaEventRecord(g_ctx.evT, s2);     // tab done
    cudaStreamWaitEvent(s2, g_ctx.evV, 0);
    if (out_size >= REC_ELEMS + NTOKENS_TOTAL + 1)
        finalize_kernel<<<(NTOKENS_TOTAL + 255) / 256, 256, 0, s2>>>(out);

    // default waits for tab, then decoder
    cudaStreamWaitEvent(0, g_ctx.evT, 0);
    gather_sum<<<NB, 256>>>(db1, h3h, h3l);
    gemm_bf<1, 1><<<dim3(HID / 128,    NB / 128), 256, GEMM_SMEM>>>(
        h3h, h3l, wh + OFF_DW2, wl + OFF_DW2, db2, nullptr, h4h, h4l, NB, HID, HID);
    gemm_bf<0, 0><<<dim3(IN_DIM / 128, NB / 128), 256, GEMM_SMEM>>>(
        h4h, h4l, wh + OFF_DW3, wl + OFF_DW3, db3, out, nullptr, nullptr, NB, HID, IN_DIM);

    // join s2 back into default
    cudaEventRecord(g_ctx.evF, s2);
    cudaStreamWaitEvent(0, g_ctx.evF, 0);
}

// round 11
// speedup vs baseline: 1.1529x; 1.0258x over previous
#include <cuda_runtime.h>
#include <cuda_bf16.h>
#include <math.h>

#define NB 4096
#define IN_DIM 1024
#define HID 512
#define EMBED 128
#define NTOK 16
#define NCODES 1024
#define LATENT 2048
#define NTOKENS_TOTAL (NB * NTOK)          // 65536
#define QELEMS (NTOKENS_TOTAL * EMBED)     // 8388608
#define REC_ELEMS (NB * IN_DIM)            // 4194304

// weight pool offsets (elements) — transposed [N][K] layouts
#define OFF_EW1 0
#define OFF_EW2 524288
#define OFF_EW3 786432
#define OFF_DW1 1835008
#define OFF_DW2 2883584
#define OFF_DW3 3145728
#define OFF_CB  3670016
#define WPOOL_N 3801088

// ------------------------- streams/events (created once at load) -------------------------
struct GraphCtx {
    cudaStream_t s2;
    cudaEvent_t ev0, evA, evB, evT, evV, evF;
    GraphCtx() {
        cudaStreamCreateWithFlags(&s2, cudaStreamNonBlocking);
        cudaEventCreateWithFlags(&ev0, cudaEventDisableTiming);
        cudaEventCreateWithFlags(&evA, cudaEventDisableTiming);
        cudaEventCreateWithFlags(&evB, cudaEventDisableTiming);
        cudaEventCreateWithFlags(&evT, cudaEventDisableTiming);
        cudaEventCreateWithFlags(&evV, cudaEventDisableTiming);
        cudaEventCreateWithFlags(&evF, cudaEventDisableTiming);
    }
};
static GraphCtx g_ctx;

// ------------------------- scratch -------------------------
__device__ __nv_bfloat16 g_xh[NB * IN_DIM];
__device__ __nv_bfloat16 g_xl[NB * IN_DIM];
__device__ __nv_bfloat16 g_h1h[NB * HID];
__device__ __nv_bfloat16 g_h1l[NB * HID];
__device__ __nv_bfloat16 g_h2h[NB * HID];
__device__ __nv_bfloat16 g_h2l[NB * HID];
__device__ __nv_bfloat16 g_h3h[NB * HID];
__device__ __nv_bfloat16 g_h3l[NB * HID];
__device__ __nv_bfloat16 g_h4h[NB * HID];
__device__ __nv_bfloat16 g_h4l[NB * HID];
__device__ __nv_bfloat16 g_wh[WPOOL_N];
__device__ __nv_bfloat16 g_wl[WPOOL_N];
__device__ float  g_T[NTOK * NCODES * HID];   // 33.5 MB code table
__device__ float  g_cnorm[NCODES];
__device__ int    g_idx[NTOKENS_TOTAL];
__device__ double g_loss;

__device__ __forceinline__ float gelu_exact(float x) {
    return 0.5f * x * (1.0f + erff(x * 0.70710678118654752440f));
}

__device__ __forceinline__ void mma16(float* d,
                                      unsigned a0, unsigned a1, unsigned a2, unsigned a3,
                                      unsigned b0, unsigned b1) {
    asm volatile(
        "mma.sync.aligned.m16n8k16.row.col.f32.bf16.bf16.f32 "
        "{%0,%1,%2,%3},{%4,%5,%6,%7},{%8,%9},{%0,%1,%2,%3};"
        : "+f"(d[0]), "+f"(d[1]), "+f"(d[2]), "+f"(d[3])
        : "r"(a0), "r"(a1), "r"(a2), "r"(a3), "r"(b0), "r"(b1));
}

__device__ __forceinline__ void ldm4(unsigned &r0, unsigned &r1, unsigned &r2, unsigned &r3,
                                     unsigned addr) {
    asm volatile("ldmatrix.sync.aligned.m8n8.x4.shared.b16 {%0,%1,%2,%3}, [%4];"
                 : "=r"(r0), "=r"(r1), "=r"(r2), "=r"(r3) : "r"(addr));
}

__device__ __forceinline__ void cpa16u(unsigned dst, const __nv_bfloat16* src) {
    asm volatile("cp.async.cg.shared.global [%0], [%1], 16;" :: "r"(dst), "l"(src));
}
#define CPA_COMMIT() asm volatile("cp.async.commit_group;")
#define CPA_WAIT0()  asm volatile("cp.async.wait_group 0;")
#define CPA_WAIT1()  asm volatile("cp.async.wait_group 1;")

// ------------------------- prep kernels -------------------------
__device__ __forceinline__ void split_f4(float4 v, __nv_bfloat16* hi, __nv_bfloat16* lo, int i) {
    __nv_bfloat16 h0 = __float2bfloat16(v.x);
    __nv_bfloat16 h1 = __float2bfloat16(v.y);
    __nv_bfloat16 h2 = __float2bfloat16(v.z);
    __nv_bfloat16 h3 = __float2bfloat16(v.w);
    __nv_bfloat162 hh0; hh0.x = h0; hh0.y = h1;
    __nv_bfloat162 hh1; hh1.x = h2; hh1.y = h3;
    __nv_bfloat162 ll0;
    ll0.x = __float2bfloat16(v.x - __bfloat162float(h0));
    ll0.y = __float2bfloat16(v.y - __bfloat162float(h1));
    __nv_bfloat162 ll1;
    ll1.x = __float2bfloat16(v.z - __bfloat162float(h2));
    ll1.y = __float2bfloat16(v.w - __bfloat162float(h3));
    ((__nv_bfloat162*)hi)[i * 2]     = hh0;
    ((__nv_bfloat162*)hi)[i * 2 + 1] = hh1;
    ((__nv_bfloat162*)lo)[i * 2]     = ll0;
    ((__nv_bfloat162*)lo)[i * 2 + 1] = ll1;
}

#define X4  (NB * IN_DIM / 4)       // 1048576
#define CB4 (NCODES * EMBED / 4)    // 32768

__global__ void pack_all(const float* __restrict__ x, const float* __restrict__ cb,
                         __nv_bfloat16* __restrict__ xh, __nv_bfloat16* __restrict__ xl,
                         __nv_bfloat16* __restrict__ ch, __nv_bfloat16* __restrict__ cl)
{
    int i = blockIdx.x * blockDim.x + threadIdx.x;
    if (i < X4) {
        split_f4(((const float4*)x)[i], xh, xl, i);
    } else if (i < X4 + CB4) {
        int j = i - X4;
        split_f4(((const float4*)cb)[j], ch, cl, j);
    }
}

__global__ void packT_all(const float* __restrict__ eW1, const float* __restrict__ eW2,
                          const float* __restrict__ eW3, const float* __restrict__ dW1,
                          const float* __restrict__ dW2, const float* __restrict__ dW3)
{
    __shared__ float t[32][33];
    int bid = blockIdx.x;
    const float* W; int K, N, off, lt;
    if      (bid < 512)  { W = eW1; K = IN_DIM; N = HID;    off = OFF_EW1; lt = bid; }
    else if (bid < 768)  { W = eW2; K = HID;    N = HID;    off = OFF_EW2; lt = bid - 512; }
    else if (bid < 1792) { W = eW3; K = HID;    N = LATENT; off = OFF_EW3; lt = bid - 768; }
    else if (bid < 2816) { W = dW1; K = LATENT; N = HID;    off = OFF_DW1; lt = bid - 1792; }
    else if (bid < 3072) { W = dW2; K = HID;    N = HID;    off = OFF_DW2; lt = bid - 2816; }
    else                 { W = dW3; K = HID;    N = IN_DIM; off = OFF_DW3; lt = bid - 3072; }
    const int ntn = N >> 5;
    const int n0 = (lt % ntn) * 32, k0 = (lt / ntn) * 32;
    const int tx = threadIdx.x, ty = threadIdx.y;
    #pragma unroll
    for (int r = 0; r < 32; r += 8)
        t[ty + r][tx] = W[(size_t)(k0 + ty + r) * N + n0 + tx];
    __syncthreads();
    #pragma unroll
    for (int r = 0; r < 32; r += 8) {
        float v = t[tx][ty + r];
        size_t o = (size_t)off + (size_t)(n0 + ty + r) * K + k0 + tx;
        __nv_bfloat16 h = __float2bfloat16(v);
        g_wh[o] = h;
        g_wl[o] = __float2bfloat16(v - __bfloat162float(h));
    }
}

__global__ void code_norm_kernel(const float* __restrict__ cb) {
    int c = blockIdx.x * blockDim.x + threadIdx.x;
    if (c == 0) g_loss = 0.0;
    if (c < NCODES) {
        float s = 0.f;
        #pragma unroll 4
        for (int d = 0; d < EMBED; d++) {
            float v = cb[c * EMBED + d];
            s = fmaf(v, v, s);
        }
        g_cnorm[c] = s;
    }
}

// =========================================================================
// bf16 3-term GEMM, cp.async 3-stage, 256 thr (8 warps 2x4), ldmatrix.
// =========================================================================
#define GPLANE 5120                  // 128*40 elems
#define GSTAGE (4 * GPLANE)          // 20480 elems
#define GEMM_SMEM (3 * GSTAGE * 2)   // 122880 bytes

template <int ACT, int SPLIT>
__global__ __launch_bounds__(256, 1)
void gemm_bf(const __nv_bfloat16* __restrict__ Ah, const __nv_bfloat16* __restrict__ Al,
             const __nv_bfloat16* __restrict__ Wh, const __nv_bfloat16* __restrict__ Wl,
             const float* __restrict__ bias,
             float* __restrict__ C,
             __nv_bfloat16* __restrict__ Ch, __nv_bfloat16* __restrict__ Cl,
             int M, int K, int N)
{
    extern __shared__ __align__(16) char smraw[];
    const unsigned smu = (unsigned)__cvta_generic_to_shared(smraw);

    const int tid  = threadIdx.x;
    const int m0   = blockIdx.y * 128;
    const int n0   = blockIdx.x * 128;
    const int warp = tid >> 5, lane = tid & 31;
    const int mw = (warp & 1) * 64;
    const int nw = (warp >> 1) * 32;
    const int g  = lane >> 2;
    const int tq = lane & 3;

    const int lmr = lane & 15, lmk = (lane >> 4) * 8;
    const int brow = ((lane >> 4) << 3) + (lane & 7);
    const int bk8  = ((lane >> 3) & 1) << 3;

    const __nv_bfloat16* sp0 = Ah + (size_t)m0 * K;
    const __nv_bfloat16* sp1 = Al + (size_t)m0 * K;
    const __nv_bfloat16* sp2 = Wh + (size_t)n0 * K;
    const __nv_bfloat16* sp3 = Wl + (size_t)n0 * K;

    const int KT = K >> 5;

    auto fill = [&](int kt, int s) {
        const __nv_bfloat16* sp[4] = { sp0 + kt * 32, sp1 + kt * 32, sp2 + kt * 32, sp3 + kt * 32 };
        #pragma unroll
        for (int l = 0; l < 8; l++) {
            int c = l * 256 + tid;
            int p = c >> 9;
            int r = (c >> 2) & 127;
            int q = c & 3;
            cpa16u(smu + (unsigned)(s * GSTAGE + p * GPLANE + r * 40 + q * 8) * 2,
                   sp[p] + (size_t)r * K + q * 8);
        }
        CPA_COMMIT();
    };

    fill(0, 0);
    fill(1, 1);

    float acc[4][4][4] = {};

    for (int kt = 0; kt < KT; kt++) {
        if (kt + 1 < KT) { CPA_WAIT1(); } else { CPA_WAIT0(); }
        __syncthreads();
        if (kt + 2 < KT) fill(kt + 2, (kt + 2) % 3);

        const int s = kt % 3;
        const unsigned aHb = smu + (unsigned)(s * GSTAGE) * 2;
        const unsigned aLb = aHb + (unsigned)GPLANE * 2;
        const unsigned wHb = aLb + (unsigned)GPLANE * 2;
        const unsigned wLb = wHb + (unsigned)GPLANE * 2;
        #pragma unroll
        for (int ks = 0; ks < 32; ks += 16) {
            unsigned ahr[4][4], alr[4][4];
            #pragma unroll
            for (int i = 0; i < 4; i++) {
                const unsigned eo = (unsigned)((mw + i * 16 + lmr) * 40 + ks + lmk) * 2;
                ldm4(ahr[i][0], ahr[i][1], ahr[i][2], ahr[i][3], aHb + eo);
                ldm4(alr[i][0], alr[i][1], alr[i][2], alr[i][3], aLb + eo);
            }
            unsigned bhr[4][2], blr[4][2];
            #pragma unroll
            for (int jp = 0; jp < 2; jp++) {
                const unsigned eo = (unsigned)((nw + jp * 16 + brow) * 40 + ks + bk8) * 2;
                ldm4(bhr[jp*2][0], bhr[jp*2][1], bhr[jp*2+1][0], bhr[jp*2+1][1], wHb + eo);
                ldm4(blr[jp*2][0], blr[jp*2][1], blr[jp*2+1][0], blr[jp*2+1][1], wLb + eo);
            }
            #pragma unroll
            for (int i = 0; i < 4; i++)
                #pragma unroll
                for (int j = 0; j < 4; j++) {
                    mma16(acc[i][j], ahr[i][0], ahr[i][1], ahr[i][2], ahr[i][3], bhr[j][0], bhr[j][1]);
                    mma16(acc[i][j], ahr[i][0], ahr[i][1], ahr[i][2], ahr[i][3], blr[j][0], blr[j][1]);
                    mma16(acc[i][j], alr[i][0], alr[i][1], alr[i][2], alr[i][3], bhr[j][0], bhr[j][1]);
                }
        }
        __syncthreads();
    }

    #pragma unroll
    for (int j = 0; j < 4; j++) {
        const int col = n0 + nw + j * 8 + tq * 2;
        const float b0 = bias[col], b1 = bias[col + 1];
        #pragma unroll
        for (int i = 0; i < 4; i++) {
            const int r = m0 + mw + i * 16 + g;
            float v0 = acc[i][j][0] + b0;
            float v1 = acc[i][j][1] + b1;
            float v2 = acc[i][j][2] + b0;
            float v3 = acc[i][j][3] + b1;
            if (ACT) { v0 = gelu_exact(v0); v1 = gelu_exact(v1); v2 = gelu_exact(v2); v3 = gelu_exact(v3); }
            const size_t o0 = (size_t)r * N + col;
            const size_t o1 = (size_t)(r + 8) * N + col;
            if (SPLIT) {
                __nv_bfloat16 h0 = __float2bfloat16(v0), h1 = __float2bfloat16(v1);
                __nv_bfloat16 h2 = __float2bfloat16(v2), h3 = __float2bfloat16(v3);
                __nv_bfloat162 hh0; hh0.x = h0; hh0.y = h1;
                __nv_bfloat162 hh1; hh1.x = h2; hh1.y = h3;
                __nv_bfloat162 ll0;
                ll0.x = __float2bfloat16(v0 - __bfloat162float(h0));
                ll0.y = __float2bfloat16(v1 - __bfloat162float(h1));
                __nv_bfloat162 ll1;
                ll1.x = __float2bfloat16(v2 - __bfloat162float(h2));
                ll1.y = __float2bfloat16(v3 - __bfloat162float(h3));
                *(__nv_bfloat162*)&Ch[o0] = hh0;
                *(__nv_bfloat162*)&Ch[o1] = hh1;
                *(__nv_bfloat162*)&Cl[o0] = ll0;
                *(__nv_bfloat162*)&Cl[o1] = ll1;
            } else {
                *(float2*)&C[o0] = make_float2(v0, v1);
                *(float2*)&C[o1] = make_float2(v2, v3);
            }
        }
    }
}

// =========================================================================
// Code table: T[t][c][n] = cb[c] @ dW1[t*128:(t+1)*128, n]
// =========================================================================
__global__ __launch_bounds__(256, 1)
void gemm_tab(const __nv_bfloat16* __restrict__ Ah, const __nv_bfloat16* __restrict__ Al,
              const __nv_bfloat16* __restrict__ Wh, const __nv_bfloat16* __restrict__ Wl)
{
    extern __shared__ __align__(16) char smraw[];
    const unsigned smu = (unsigned)__cvta_generic_to_shared(smraw);

    const int tid  = threadIdx.x;
    const int m0   = blockIdx.y * 128;
    const int n0   = blockIdx.x * 128;
    const int tt   = blockIdx.z;
    const int warp = tid >> 5, lane = tid & 31;
    const int mw = (warp & 1) * 64;
    const int nw = (warp >> 1) * 32;
    const int g  = lane >> 2;
    const int tq = lane & 3;

    const int lmr = lane & 15, lmk = (lane >> 4) * 8;
    const int brow = ((lane >> 4) << 3) + (lane & 7);
    const int bk8  = ((lane >> 3) & 1) << 3;

    const int AK = EMBED;
    const int WK = LATENT;
    const int koff = tt * EMBED;

    const __nv_bfloat16* sp0 = Ah + (size_t)m0 * AK;
    const __nv_bfloat16* sp1 = Al + (size_t)m0 * AK;
    const __nv_bfloat16* sp2 = Wh + (size_t)n0 * WK + koff;
    const __nv_bfloat16* sp3 = Wl + (size_t)n0 * WK + koff;

    const int KT = 4;

    auto fill = [&](int kt, int s) {
        #pragma unroll
        for (int l = 0; l < 8; l++) {
            int c = l * 256 + tid;
            int p = c >> 9;
            int r = (c >> 2) & 127;
            int q = c & 3;
            const __nv_bfloat16* src;
            if (p == 0)      src = sp0 + (size_t)r * AK;
            else if (p == 1) src = sp1 + (size_t)r * AK;
            else if (p == 2) src = sp2 + (size_t)r * WK;
            else             src = sp3 + (size_t)r * WK;
            cpa16u(smu + (unsigned)(s * GSTAGE + p * GPLANE + r * 40 + q * 8) * 2,
                   src + kt * 32 + q * 8);
        }
        CPA_COMMIT();
    };

    fill(0, 0);
    fill(1, 1);

    float acc[4][4][4] = {};

    for (int kt = 0; kt < KT; kt++) {
        if (kt + 1 < KT) { CPA_WAIT1(); } else { CPA_WAIT0(); }
        __syncthreads();
        if (kt + 2 < KT) fill(kt + 2, (kt + 2) % 3);

        const int s = kt % 3;
        const unsigned aHb = smu + (unsigned)(s * GSTAGE) * 2;
        const unsigned aLb = aHb + (unsigned)GPLANE * 2;
        const unsigned wHb = aLb + (unsigned)GPLANE * 2;
        const unsigned wLb = wHb + (unsigned)GPLANE * 2;
        #pragma unroll
        for (int ks = 0; ks < 32; ks += 16) {
            unsigned ahr[4][4], alr[4][4];
            #pragma unroll
            for (int i = 0; i < 4; i++) {
                const unsigned eo = (unsigned)((mw + i * 16 + lmr) * 40 + ks + lmk) * 2;
                ldm4(ahr[i][0], ahr[i][1], ahr[i][2], ahr[i][3], aHb + eo);
                ldm4(alr[i][0], alr[i][1], alr[i][2], alr[i][3], aLb + eo);
            }
            unsigned bhr[4][2], blr[4][2];
            #pragma unroll
            for (int jp = 0; jp < 2; jp++) {
                const unsigned eo = (unsigned)((nw + jp * 16 + brow) * 40 + ks + bk8) * 2;
                ldm4(bhr[jp*2][0], bhr[jp*2][1], bhr[jp*2+1][0], bhr[jp*2+1][1], wHb + eo);
                ldm4(blr[jp*2][0], blr[jp*2][1], blr[jp*2+1][0], blr[jp*2+1][1], wLb + eo);
            }
            #pragma unroll
            for (int i = 0; i < 4; i++)
                #pragma unroll
                for (int j = 0; j < 4; j++) {
                    mma16(acc[i][j], ahr[i][0], ahr[i][1], ahr[i][2], ahr[i][3], bhr[j][0], bhr[j][1]);
                    mma16(acc[i][j], ahr[i][0], ahr[i][1], ahr[i][2], ahr[i][3], blr[j][0], blr[j][1]);
                    mma16(acc[i][j], alr[i][0], alr[i][1], alr[i][2], alr[i][3], bhr[j][0], bhr[j][1]);
                }
        }
        __syncthreads();
    }

    float* Tout = g_T + (size_t)tt * NCODES * HID;
    #pragma unroll
    for (int j = 0; j < 4; j++) {
        const int col = n0 + nw + j * 8 + tq * 2;
        #pragma unroll
        for (int i = 0; i < 4; i++) {
            const int r = m0 + mw + i * 16 + g;
            *(float2*)&Tout[(size_t)r * HID + col]       = make_float2(acc[i][j][0], acc[i][j][1]);
            *(float2*)&Tout[(size_t)(r + 8) * HID + col] = make_float2(acc[i][j][2], acc[i][j][3]);
        }
    }
}

// =========================================================================
// FUSED enc3 + VQ.
// grid (NTOK=16 token-cols, NB/128=32 batch-blocks), 256 threads.
// Phase 1: z-tile GEMM (K=512), stages in smem region B.
// Phase 2: VQ vs full codebook; codebook double-buffer aliases region B.
// smem: [B: 139264][ZsH/ZsL: 69632][cn: 4096] = 212992 bytes.
// =========================================================================
#define ZPS 17408                      // 128*136 bf16 elems
#define FUSE_B  139264
#define FUSE_Z  FUSE_B
#define FUSE_CN (FUSE_B + 2 * ZPS * 2)   // 208896
#define FUSE_SMEM (FUSE_CN + NCODES * 4) // 212992

__global__ __launch_bounds__(256, 1)
void enc3_vq(const __nv_bfloat16* __restrict__ Ah, const __nv_bfloat16* __restrict__ Al,
             const __nv_bfloat16* __restrict__ Wh, const __nv_bfloat16* __restrict__ Wl,
             const float* __restrict__ bias,
             const __nv_bfloat16* __restrict__ cbh, const __nv_bfloat16* __restrict__ cbl,
             const float* __restrict__ cb)
{
    extern __shared__ __align__(16) char smraw[];
    const unsigned smu = (unsigned)__cvta_generic_to_shared(smraw);
    __nv_bfloat16* ZsH = (__nv_bfloat16*)(smraw + FUSE_Z);
    __nv_bfloat16* ZsL = ZsH + ZPS;
    float* cn = (float*)(smraw + FUSE_CN);
    const unsigned zHb = smu + FUSE_Z;
    const unsigned zLb = zHb + (unsigned)ZPS * 2;

    __shared__ float red_d[128][4];
    __shared__ int   red_i[128][4];
    __shared__ int   best_idx[128];
    __shared__ float warp_sum[8];

    const int tid  = threadIdx.x;
    const int tt   = blockIdx.x;           // token index (latent col block)
    const int m0   = blockIdx.y * 128;      // batch rows
    const int n0   = tt * 128;              // latent col offset
    const int warp = tid >> 5, lane = tid & 31;
    const int mw = (warp & 1) * 64;
    const int nw = (warp >> 1) * 32;
    const int g  = lane >> 2;
    const int tq = lane & 3;

    const int lmr = lane & 15, lmk = (lane >> 4) * 8;
    const int brow = ((lane >> 4) << 3) + (lane & 7);
    const int bk8  = ((lane >> 3) & 1) << 3;

    // cnorm (region A — free throughout)
    *(float4*)&cn[tid * 4] = *(const float4*)&g_cnorm[tid * 4];

    // ---------------- Phase 1: GEMM (K=512) ----------------
    const __nv_bfloat16* sp0 = Ah + (size_t)m0 * HID;
    const __nv_bfloat16* sp1 = Al + (size_t)m0 * HID;
    const __nv_bfloat16* sp2 = Wh + (size_t)n0 * HID;
    const __nv_bfloat16* sp3 = Wl + (size_t)n0 * HID;
    const int KT = HID >> 5;   // 16

    auto fill = [&](int kt, int s) {
        const __nv_bfloat16* sp[4] = { sp0 + kt * 32, sp1 + kt * 32, sp2 + kt * 32, sp3 + kt * 32 };
        #pragma unroll
        for (int l = 0; l < 8; l++) {
            int c = l * 256 + tid;
            int p = c >> 9;
            int r = (c >> 2) & 127;
            int q = c & 3;
            cpa16u(smu + (unsigned)(s * GSTAGE + p * GPLANE + r * 40 + q * 8) * 2,
                   sp[p] + (size_t)r * HID + q * 8);
        }
        CPA_COMMIT();
    };

    fill(0, 0);
    fill(1, 1);

    float acc[4][4][4] = {};

    for (int kt = 0; kt < KT; kt++) {
        if (kt + 1 < KT) { CPA_WAIT1(); } else { CPA_WAIT0(); }
        __syncthreads();
        if (kt + 2 < KT) fill(kt + 2, (kt + 2) % 3);

        const int s = kt % 3;
        const unsigned aHb = smu + (unsigned)(s * GSTAGE) * 2;
        const unsigned aLb = aHb + (unsigned)GPLANE * 2;
        const unsigned wHb = aLb + (unsigned)GPLANE * 2;
        const unsigned wLb = wHb + (unsigned)GPLANE * 2;
        #pragma unroll
        for (int ks = 0; ks < 32; ks += 16) {
            unsigned ahr[4][4], alr[4][4];
            #pragma unroll
            for (int i = 0; i < 4; i++) {
                const unsigned eo = (unsigned)((mw + i * 16 + lmr) * 40 + ks + lmk) * 2;
                ldm4(ahr[i][0], ahr[i][1], ahr[i][2], ahr[i][3], aHb + eo);
                ldm4(alr[i][0], alr[i][1], alr[i][2], alr[i][3], aLb + eo);
            }
            unsigned bhr[4][2], blr[4][2];
            #pragma unroll
            for (int jp = 0; jp < 2; jp++) {
                const unsigned eo = (unsigned)((nw + jp * 16 + brow) * 40 + ks + bk8) * 2;
                ldm4(bhr[jp*2][0], bhr[jp*2][1], bhr[jp*2+1][0], bhr[jp*2+1][1], wHb + eo);
                ldm4(blr[jp*2][0], blr[jp*2][1], blr[jp*2+1][0], blr[jp*2+1][1], wLb + eo);
            }
            #pragma unroll
            for (int i = 0; i < 4; i++)
                #pragma unroll
                for (int j = 0; j < 4; j++) {
                    mma16(acc[i][j], ahr[i][0], ahr[i][1], ahr[i][2], ahr[i][3], bhr[j][0], bhr[j][1]);
                    mma16(acc[i][j], ahr[i][0], ahr[i][1], ahr[i][2], ahr[i][3], blr[j][0], blr[j][1]);
                    mma16(acc[i][j], alr[i][0], alr[i][1], alr[i][2], alr[i][3], bhr[j][0], bhr[j][1]);
                }
        }
        __syncthreads();
    }

    // z epilogue -> smem planes (bias + split, identical math to gemm_bf<0,1>)
    #pragma unroll
    for (int j = 0; j < 4; j++) {
        const int col = nw + j * 8 + tq * 2;      // within-tile latent dim
        const float b0 = bias[n0 + col], b1 = bias[n0 + col + 1];
        #pragma unroll
        for (int i = 0; i < 4; i++) {
            const int r = mw + i * 16 + g;        // within-tile token row
            float v0 = acc[i][j][0] + b0;
            float v1 = acc[i][j][1] + b1;
            float v2 = acc[i][j][2] + b0;
            float v3 = acc[i][j][3] + b1;
            __nv_bfloat16 h0 = __float2bfloat16(v0), h1 = __float2bfloat16(v1);
            __nv_bfloat16 h2 = __float2bfloat16(v2), h3 = __float2bfloat16(v3);
            __nv_bfloat162 hh0; hh0.x = h0; hh0.y = h1;
            __nv_bfloat162 hh1; hh1.x = h2; hh1.y = h3;
            __nv_bfloat162 ll0;
            ll0.x = __float2bfloat16(v0 - __bfloat162float(h0));
            ll0.y = __float2bfloat16(v1 - __bfloat162float(h1));
            __nv_bfloat162 ll1;
            ll1.x = __float2bfloat16(v2 - __bfloat162float(h2));
            ll1.y = __float2bfloat16(v3 - __bfloat162float(h3));
            *(__nv_bfloat162*)&ZsH[r * 136 + col]       = hh0;
            *(__nv_bfloat162*)&ZsH[(r + 8) * 136 + col] = hh1;
            *(__nv_bfloat162*)&ZsL[r * 136 + col]       = ll0;
            *(__nv_bfloat162*)&ZsL[(r + 8) * 136 + col] = ll1;
        }
    }
    __syncthreads();

    // ---------------- Phase 2: VQ (codebook aliases region B) ----------------
    auto fill_cb = [&](int c0n, int buf) {
        unsigned dH = smu + (unsigned)(buf * 2 * ZPS) * 2;
        unsigned dL = dH + (unsigned)ZPS * 2;
        #pragma unroll
        for (int l = 0; l < 8; l++) {
            int idx = l * 256 + tid;
            int row = idx >> 4, c16 = (idx & 15) * 8;
            cpa16u(dH + (unsigned)(row * 136 + c16) * 2, cbh + (size_t)(c0n + row) * EMBED + c16);
            cpa16u(dL + (unsigned)(row * 136 + c16) * 2, cbl + (size_t)(c0n + row) * EMBED + c16);
        }
        CPA_COMMIT();
    };

    fill_cb(0, 0);
    CPA_WAIT0();
    __syncthreads();

    float bestD[8];
    int   bestI[8];
    #pragma unroll
    for (int s = 0; s < 8; s++) { bestD[s] = 3.4e38f; bestI[s] = 0; }

    for (int ct = 0; ct < 8; ct++) {
        const int cur = ct & 1, nxt = cur ^ 1;
        const unsigned cHb = smu + (unsigned)(cur * 2 * ZPS) * 2;
        const unsigned cLb = cHb + (unsigned)ZPS * 2;

        if (ct < 7) fill_cb((ct + 1) * 128, nxt);

        float vacc[4][4][4] = {};
        #pragma unroll
        for (int kt = 0; kt < 8; kt++) {
            const int kb = kt * 16;
            unsigned ahr[4][4], alr[4][4];
            #pragma unroll
            for (int i = 0; i < 4; i++) {
                const unsigned eo = (unsigned)((mw + i * 16 + lmr) * 136 + kb + lmk) * 2;
                ldm4(ahr[i][0], ahr[i][1], ahr[i][2], ahr[i][3], zHb + eo);
                ldm4(alr[i][0], alr[i][1], alr[i][2], alr[i][3], zLb + eo);
            }
            unsigned bhr[4][2], blr[4][2];
            #pragma unroll
            for (int jp = 0; jp < 2; jp++) {
                const unsigned eo = (unsigned)((nw + jp * 16 + brow) * 136 + kb + bk8) * 2;
                ldm4(bhr[jp*2][0], bhr[jp*2][1], bhr[jp*2+1][0], bhr[jp*2+1][1], cHb + eo);
                ldm4(blr[jp*2][0], blr[jp*2][1], blr[jp*2+1][0], blr[jp*2+1][1], cLb + eo);
            }
            #pragma unroll
            for (int i = 0; i < 4; i++)
                #pragma unroll
                for (int j = 0; j < 4; j++) {
                    mma16(vacc[i][j], ahr[i][0], ahr[i][1], ahr[i][2], ahr[i][3], bhr[j][0], bhr[j][1]);
                    mma16(vacc[i][j], ahr[i][0], ahr[i][1], ahr[i][2], ahr[i][3], blr[j][0], blr[j][1]);
                    mma16(vacc[i][j], alr[i][0], alr[i][1], alr[i][2], alr[i][3], bhr[j][0], bhr[j][1]);
                }
        }

        const int c0 = ct * 128;
        #pragma unroll
        for (int j = 0; j < 4; j++) {
            const int cbase = c0 + nw + j * 8 + tq * 2;
            const float cn0 = cn[cbase], cn1 = cn[cbase + 1];
            #pragma unroll
            for (int i = 0; i < 4; i++) {
                #pragma unroll
                for (int h = 0; h < 2; h++) {
                    const int s = i * 2 + h;
                    float d0 = fmaf(-2.0f, vacc[i][j][h * 2 + 0], cn0);
                    float d1 = fmaf(-2.0f, vacc[i][j][h * 2 + 1], cn1);
                    if (d0 < bestD[s] || (d0 == bestD[s] && cbase < bestI[s])) { bestD[s] = d0; bestI[s] = cbase; }
                    if (d1 < bestD[s] || (d1 == bestD[s] && cbase + 1 < bestI[s])) { bestD[s] = d1; bestI[s] = cbase + 1; }
                }
            }
        }

        if (ct < 7) {
            CPA_WAIT0();
            __syncthreads();
        }
    }

    // lane reduce across tq
    #pragma unroll
    for (int s = 0; s < 8; s++) {
        #pragma unroll
        for (int o = 1; o < 4; o <<= 1) {
            float od = __shfl_xor_sync(0xFFFFFFFFu, bestD[s], o);
            int   oi = __shfl_xor_sync(0xFFFFFFFFu, bestI[s], o);
            if (od < bestD[s] || (od == bestD[s] && oi < bestI[s])) { bestD[s] = od; bestI[s] = oi; }
        }
    }
    if (tq == 0) {
        #pragma unroll
        for (int s = 0; s < 8; s++) {
            const int row = mw + (s >> 1) * 16 + (s & 1) * 8 + g;
            red_d[row][warp >> 1] = bestD[s];
            red_i[row][warp >> 1] = bestI[s];
        }
    }
    __syncthreads();
    if (tid < 128) {
        float bd = red_d[tid][0];
        int   bi = red_i[tid][0];
        #pragma unroll
        for (int x = 1; x < 4; x++) {
            float d = red_d[tid][x];
            int   c = red_i[tid][x];
            if (d < bd || (d == bd && c < bi)) { bd = d; bi = c; }
        }
        best_idx[tid] = bi;
        g_idx[(size_t)(m0 + tid) * NTOK + tt] = bi;
    }
    __syncthreads();

    // commit loss
    float lsum = 0.f;
    #pragma unroll 4
    for (int l = 0; l < 64; l++) {
        int e = l * 256 + tid;
        int trow = e >> 7;
        int d    = e & 127;
        int c    = best_idx[trow];
        float zv = __bfloat162float(ZsH[trow * 136 + d]) + __bfloat162float(ZsL[trow * 136 + d]);
        float diff = cb[(size_t)c * EMBED + d] - zv;
        lsum = fmaf(diff, diff, lsum);
    }
    #pragma unroll
    for (int o = 16; o > 0; o >>= 1) lsum += __shfl_down_sync(0xFFFFFFFFu, lsum, o);
    if (lane == 0) warp_sum[warp] = lsum;
    __syncthreads();
    if (tid == 0) {
        float s = 0.f;
        #pragma unroll
        for (int w = 0; w < 8; w++) s += warp_sum[w];
        atomicAdd(&g_loss, (double)s);
    }
}

// =========================================================================
// gather-sum: h3[b] = gelu( sum_t T[t][idx[b,t]] + db1 )
// =========================================================================
__global__ __launch_bounds__(256)
void gather_sum(const float* __restrict__ db1,
                __nv_bfloat16* __restrict__ h3h, __nv_bfloat16* __restrict__ h3l)
{
    __shared__ int sidx[16];
    const int b = blockIdx.x;
    const int tid = threadIdx.x;
    if (tid < 16) sidx[tid] = g_idx[b * 16 + tid];
    __syncthreads();
    #pragma unroll
    for (int h = 0; h < 2; h++) {
        const int c = h * 256 + tid;
        float acc = 0.f;
        #pragma unroll
        for (int t = 0; t < 16; t++)
            acc += g_T[((size_t)t * NCODES + sidx[t]) * HID + c];
        float v = gelu_exact(acc + db1[c]);
        __nv_bfloat16 hh = __float2bfloat16(v);
        h3h[(size_t)b * HID + c] = hh;
        h3l[(size_t)b * HID + c] = __float2bfloat16(v - __bfloat162float(hh));
    }
}

// ------------------------- tail outputs -------------------------
__global__ void finalize_kernel(float* __restrict__ out)
{
    int i = blockIdx.x * 256 + threadIdx.x;
    if (i < NTOKENS_TOTAL) out[REC_ELEMS + i] = (float)g_idx[i];
    if (i == 0) out[REC_ELEMS + NTOKENS_TOTAL] = (float)(g_loss / (double)QELEMS);
}

// ------------------------- launch -------------------------
extern "C" void kernel_launch(void* const* d_in, const int* in_sizes, int n_in,
                              void* d_out, int out_size)
{
    const float* x   = (const float*)d_in[0];
    const float* eW1 = (const float*)d_in[1];
    const float* eb1 = (const float*)d_in[2];
    const float* eW2 = (const float*)d_in[3];
    const float* eb2 = (const float*)d_in[4];
    const float* eW3 = (const float*)d_in[5];
    const float* eb3 = (const float*)d_in[6];
    const float* dW1 = (const float*)d_in[7];
    const float* db1 = (const float*)d_in[8];
    const float* dW2 = (const float*)d_in[9];
    const float* db2 = (const float*)d_in[10];
    const float* dW3 = (const float*)d_in[11];
    const float* db3 = (const float*)d_in[12];
    const float* cb  = (const float*)d_in[13];
    float* out = (float*)d_out;

    __nv_bfloat16 *xh, *xl, *h1h, *h1l, *h2h, *h2l;
    __nv_bfloat16 *h3h, *h3l, *h4h, *h4l, *wh, *wl;
    cudaGetSymbolAddress((void**)&xh,  g_xh);
    cudaGetSymbolAddress((void**)&xl,  g_xl);
    cudaGetSymbolAddress((void**)&h1h, g_h1h);
    cudaGetSymbolAddress((void**)&h1l, g_h1l);
    cudaGetSymbolAddress((void**)&h2h, g_h2h);
    cudaGetSymbolAddress((void**)&h2l, g_h2l);
    cudaGetSymbolAddress((void**)&h3h, g_h3h);
    cudaGetSymbolAddress((void**)&h3l, g_h3l);
    cudaGetSymbolAddress((void**)&h4h, g_h4h);
    cudaGetSymbolAddress((void**)&h4l, g_h4l);
    cudaGetSymbolAddress((void**)&wh,  g_wh);
    cudaGetSymbolAddress((void**)&wl,  g_wl);

    cudaFuncSetAttribute(gemm_bf<1, 1>, cudaFuncAttributeMaxDynamicSharedMemorySize, GEMM_SMEM);
    cudaFuncSetAttribute(gemm_bf<0, 0>, cudaFuncAttributeMaxDynamicSharedMemorySize, GEMM_SMEM);
    cudaFuncSetAttribute(gemm_tab, cudaFuncAttributeMaxDynamicSharedMemorySize, GEMM_SMEM);
    cudaFuncSetAttribute(enc3_vq, cudaFuncAttributeMaxDynamicSharedMemorySize, FUSE_SMEM);

    cudaStream_t s2 = g_ctx.s2;

    // ---- fork: weights pack on s2, x/cb pack + norms on default ----
    cudaEventRecord(g_ctx.ev0, 0);
    cudaStreamWaitEvent(s2, g_ctx.ev0, 0);
    packT_all<<<3584, dim3(32, 8), 0, s2>>>(eW1, eW2, eW3, dW1, dW2, dW3);

    code_norm_kernel<<<4, 256>>>(cb);
    pack_all<<<(X4 + CB4) / 256, 256>>>(x, cb, xh, xl, wh + OFF_CB, wl + OFF_CB);

    cudaEventRecord(g_ctx.evA, 0);      // pack_all done (cb planes)
    cudaEventRecord(g_ctx.evB, s2);     // packT_all done (weights)
    cudaStreamWaitEvent(0, g_ctx.evB, 0);
    cudaStreamWaitEvent(s2, g_ctx.evA, 0);

    // branch B: code table on s2 (hidden under encoder)
    gemm_tab<<<dim3(HID / 128, NCODES / 128, NTOK), 256, GEMM_SMEM, s2>>>(
        wh + OFF_CB, wl + OFF_CB, wh + OFF_DW1, wl + OFF_DW1);

    // branch A: encoder + fused enc3+VQ on default
    gemm_bf<1, 1><<<dim3(HID / 128, NB / 128), 256, GEMM_SMEM>>>(
        xh, xl, wh + OFF_EW1, wl + OFF_EW1, eb1, nullptr, h1h, h1l, NB, IN_DIM, HID);
    gemm_bf<1, 1><<<dim3(HID / 128, NB / 128), 256, GEMM_SMEM>>>(
        h1h, h1l, wh + OFF_EW2, wl + OFF_EW2, eb2, nullptr, h2h, h2l, NB, HID, HID);

    enc3_vq<<<dim3(NTOK, NB / 128), 256, FUSE_SMEM>>>(
        h2h, h2l, wh + OFF_EW3, wl + OFF_EW3, eb3,
        wh + OFF_CB, wl + OFF_CB, cb);

    // finalize on s2 (needs VQ results; overlaps with gather/dec2)
    cudaEventRecord(g_ctx.evV, 0);      // enc3_vq done
    cudaEventRecord(g_ctx.evT, s2);     // tab done
    cudaStreamWaitEvent(s2, g_ctx.evV, 0);
    if (out_size >= REC_ELEMS + NTOKENS_TOTAL + 1)
        finalize_kernel<<<(NTOKENS_TOTAL + 255) / 256, 256, 0, s2>>>(out);

    // default waits for tab, then decoder
    cudaStreamWaitEvent(0, g_ctx.evT, 0);
    gather_sum<<<NB, 256>>>(db1, h3h, h3l);
    gemm_bf<1, 1><<<dim3(HID / 128,    NB / 128), 256, GEMM_SMEM>>>(
        h3h, h3l, wh + OFF_DW2, wl + OFF_DW2, db2, nullptr, h4h, h4l, NB, HID, HID);
    gemm_bf<0, 0><<<dim3(IN_DIM / 128, NB / 128), 256, GEMM_SMEM>>>(
        h4h, h4l, wh + OFF_DW3, wl + OFF_DW3, db3, out, nullptr, nullptr, NB, HID, IN_DIM);

    // join s2 back into default
    cudaEventRecord(g_ctx.evF, s2);
    cudaStreamWaitEvent(0, g_ctx.evF, 0);
}